// round 2
// baseline (speedup 1.0000x reference)
#include <cuda_runtime.h>
#include <math.h>

#define B   16
#define L   512
#define H   256
#define NH  8
#define HD  32
#define ND  256        // NH*HD
#define ITR 2
#define BL  (B*L)      // 8192
#define LP1 (L+1)      // 513
#define LW  (L/32)     // 16 adjacency words per row

// ---------------- device scratch (no allocs allowed) ----------------
__device__ float    g_nodes[BL*H];
__device__ float    g_xn[BL*H];
__device__ float    g_relay[B*H];
__device__ float    g_d1[NH*BL];
__device__ float    g_d2[NH*BL];
__device__ float    g_ei[NH*BL];
__device__ float    g_ej[NH*BL];
__device__ float    g_gdat[BL*ND];
__device__ float    g_gbuf[BL*ND];
__device__ float    g_temp[BL*ND];
__device__ float    g_wa1[NH*H];
__device__ float    g_wa2[NH*H];
__device__ float    g_c1[NH];
__device__ float    g_c2[NH];
__device__ float    g_bqF[ND];
__device__ float    g_Mcat[H*ND];
__device__ float    g_Gw[H*ND];
__device__ float    g_Hw[H*ND];
__device__ unsigned g_adj[BL*LW];
__device__ float    g_r1[NH*B];
__device__ float    g_r2[NH*B];
__device__ float    g_grel[B*ND];
__device__ float    g_kproj[B*LP1*ND];
__device__ float    g_qproj[B*ND];
__device__ float    g_attv[B*ND];

__device__ __forceinline__ float warp_sum(float v) {
    #pragma unroll
    for (int o = 16; o; o >>= 1) v += __shfl_xor_sync(0xffffffffu, v, o);
    return v;
}
__device__ __forceinline__ float warp_max(float v) {
    #pragma unroll
    for (int o = 16; o; o >>= 1) v = fmaxf(v, __shfl_xor_sync(0xffffffffu, v, o));
    return v;
}

// ---------------- one-time-per-launch prep ----------------

// pack adjacency (edge>0) into bitmasks, one warp per (b,i) row
__global__ void k_pack_adj(const int* __restrict__ edge) {
    int warp = (blockIdx.x * blockDim.x + threadIdx.x) >> 5;
    int lane = threadIdx.x & 31;
    if (warp >= BL) return;
    const int* row = edge + (size_t)warp * L;
    #pragma unroll
    for (int t = 0; t < LW; t++) {
        unsigned m = __ballot_sync(0xffffffffu, row[t*32 + lane] > 0);
        if (lane == 0) g_adj[warp*LW + t] = m;
    }
}

// relay0 = mean over L of data
__global__ void k_relay0(const float* __restrict__ data) {
    int b = blockIdx.x, h = threadIdx.x;
    float s = 0.f;
    for (int l = 0; l < L; l++) s += data[((size_t)b*L + l)*H + h];
    g_relay[b*H + h] = s * (1.0f/L);
}

// wa1[n][m]=sum_k a1[n,k]*Wq[n,k,m]; c1[n]=a1[:H]·bq[n]
__global__ void k_prep_wa(const float* __restrict__ Wq, const float* __restrict__ bq,
                          const float* __restrict__ a1, const float* __restrict__ a2) {
    int n = blockIdx.x, m = threadIdx.x;
    const float* W  = Wq + (size_t)n*H*H;
    const float* A1 = a1 + n*3*H;
    const float* A2 = a2 + n*3*H;
    float s1 = 0.f, s2 = 0.f;
    for (int k = 0; k < H; k++) { float w = W[k*H + m]; s1 += A1[k]*w; s2 += A2[k]*w; }
    g_wa1[n*H + m] = s1; g_wa2[n*H + m] = s2;
    if (m == 0) {
        float c1 = 0.f, c2 = 0.f;
        for (int k = 0; k < H; k++) { c1 += A1[k]*bq[n*H + k]; c2 += A2[k]*bq[n*H + k]; }
        g_c1[n] = c1; g_c2[n] = c2;
    }
}

// bqF[n*32+d] = sum_k bq[n,k]*Fw[n,k,d]
__global__ void k_prep_bqF(const float* __restrict__ bq, const float* __restrict__ fcw) {
    int n = blockIdx.x, d = threadIdx.x;     // 32 threads
    float s = 0.f;
    for (int k = 0; k < H; k++) s += bq[n*H + k] * fcw[((size_t)n*3*H + k)*HD + d];
    g_bqF[n*HD + d] = s;
}

// Gw[k][n*32+d]=Fw[n,H+2k,d]; Hw[k][n*32+d]=Fw[n,H+2k+1,d]
__global__ void k_prep_GH(const float* __restrict__ fcw) {
    int idx = blockIdx.x*blockDim.x + threadIdx.x;
    if (idx >= H*ND) return;
    int k = idx >> 8, c = idx & 255, n = c >> 5, d = c & 31;
    g_Gw[idx] = fcw[((size_t)n*3*H + (H + 2*k    ))*HD + d];
    g_Hw[idx] = fcw[((size_t)n*3*H + (H + 2*k + 1))*HD + d];
}

// Mcat[m][n*32+d] = sum_k Wq[n,k,m]*Fw[n,k,d]
__global__ void k_prep_Mcat(const float* __restrict__ Wq, const float* __restrict__ fcw) {
    __shared__ float sF[H*HD];               // 32KB : Fw_top of this head
    int n = blockIdx.x, m = threadIdx.x;
    for (int i = m; i < H*HD; i += blockDim.x) sF[i] = fcw[(size_t)n*3*H*HD + i];
    __syncthreads();
    float acc[HD];
    #pragma unroll
    for (int d = 0; d < HD; d++) acc[d] = 0.f;
    const float* W = Wq + (size_t)n*H*H;
    for (int k = 0; k < H; k++) {
        float w = W[k*H + m];
        #pragma unroll
        for (int d = 0; d < HD; d++) acc[d] += w * sF[k*HD + d];
    }
    #pragma unroll
    for (int d = 0; d < HD; d++) g_Mcat[m*ND + n*HD + d] = acc[d];
}

// d1[n,b,l] = data[b,l]·a1[n, H+2k even]; d2 likewise — one warp per row
__global__ void k_d12(const float* __restrict__ data, const float* __restrict__ a1,
                      const float* __restrict__ a2) {
    int warp = (blockIdx.x*blockDim.x + threadIdx.x) >> 5, lane = threadIdx.x & 31;
    if (warp >= BL) return;
    float x[8];
    const float* row = data + (size_t)warp*H;
    #pragma unroll
    for (int t = 0; t < 8; t++) x[t] = row[t*32 + lane];
    for (int n = 0; n < NH; n++) {
        const float* A1 = a1 + n*3*H + H;
        const float* A2 = a2 + n*3*H + H;
        float s1 = 0.f, s2 = 0.f;
        #pragma unroll
        for (int t = 0; t < 8; t++) { int k = t*32+lane; s1 += x[t]*A1[2*k]; s2 += x[t]*A2[2*k]; }
        s1 = warp_sum(s1); s2 = warp_sum(s2);
        if (lane == 0) { g_d1[n*BL + warp] = s1; g_d2[n*BL + warp] = s2; }
    }
}

// ---------------- per-iteration kernels ----------------

__global__ void k_ln(const float* __restrict__ gamma, const float* __restrict__ beta) {
    int warp = (blockIdx.x*blockDim.x + threadIdx.x) >> 5, lane = threadIdx.x & 31;
    if (warp >= BL) return;
    float x[8];
    const float* row = g_nodes + (size_t)warp*H;
    float s = 0.f;
    #pragma unroll
    for (int t = 0; t < 8; t++) { x[t] = row[t*32 + lane]; s += x[t]; }
    s = warp_sum(s);
    float mean = s * (1.0f/H);
    float v = 0.f;
    #pragma unroll
    for (int t = 0; t < 8; t++) { float d = x[t]-mean; v += d*d; }
    v = warp_sum(v);
    float rstd = rsqrtf(v * (1.0f/H) + 1e-5f);
    #pragma unroll
    for (int t = 0; t < 8; t++) {
        int h = t*32 + lane;
        g_xn[(size_t)warp*H + h] = (x[t]-mean)*rstd*gamma[h] + beta[h];
    }
}

// relay-dependent small stuff: r1,r2, grel, qproj  (one block per b)
__global__ void k_relay_small(const float* __restrict__ a1, const float* __restrict__ a2,
                              const float* __restrict__ sqw, const float* __restrict__ sqb) {
    int b = blockIdx.x, t = threadIdx.x;     // 256 threads
    __shared__ float sr[H];
    sr[t] = g_relay[b*H + t];
    __syncthreads();
    float s = 0.f;
    for (int k = 0; k < H; k++) s += sr[k] * g_Hw[k*ND + t];
    g_grel[b*ND + t] = s;
    float q = 0.f;
    for (int h = 0; h < H; h++) q += sr[h] * sqw[(size_t)t*H + h];
    g_qproj[b*ND + t] = q + sqb[t];
    if (t < NH) {
        int n = t; float s1 = 0.f, s2 = 0.f;
        const float* A1 = a1 + n*3*H + H;
        const float* A2 = a2 + n*3*H + H;
        for (int k = 0; k < H; k++) { s1 += sr[k]*A1[2*k+1]; s2 += sr[k]*A2[2*k+1]; }
        g_r1[n*B + b] = s1; g_r2[n*B + b] = s2;
    }
}

// ei/ej per (b,l): xn·wa + d-const + relay-const + bias-const. one warp per row
__global__ void k_eij() {
    int warp = (blockIdx.x*blockDim.x + threadIdx.x) >> 5, lane = threadIdx.x & 31;
    if (warp >= BL) return;
    int b = warp >> 9;
    float x[8];
    const float* row = g_xn + (size_t)warp*H;
    #pragma unroll
    for (int t = 0; t < 8; t++) x[t] = row[t*32 + lane];
    for (int n = 0; n < NH; n++) {
        float s1 = 0.f, s2 = 0.f;
        #pragma unroll
        for (int t = 0; t < 8; t++) {
            int k = t*32+lane;
            s1 += x[t]*g_wa1[n*H + k];
            s2 += x[t]*g_wa2[n*H + k];
        }
        s1 = warp_sum(s1); s2 = warp_sum(s2);
        if (lane == 0) {
            g_ei[n*BL + warp] = s1 + g_d1[n*BL + warp] + g_r1[n*B + b] + g_c1[n];
            g_ej[n*BL + warp] = s2 + g_d2[n*BL + warp] + g_r2[n*B + b] + g_c2[n];
        }
    }
}

// ------- generic 256-K 256-N fp32 GEMM, 64x64 tile, 4x4/thread -------
// ep: 0 = C=acc(+bias)   1 = +bias+add1[r]+add2[b]   2 = C += lrelu(acc+bias,0.01)
//     3 = kproj remap row (b*513 + l + 1), C=acc+bias
__global__ __launch_bounds__(256) void k_gemm256(
        const float* __restrict__ A, const float* __restrict__ Bm,
        float* __restrict__ C, int bT, int ep,
        const float* __restrict__ bias,
        const float* __restrict__ add1, const float* __restrict__ add2) {
    __shared__ float As[16][68];
    __shared__ float Bs[16][68];
    int tid = threadIdx.x;
    int tx = tid & 15, ty = tid >> 4;
    int tm = blockIdx.x * 64, tn = blockIdx.y * 64;
    float acc[4][4];
    #pragma unroll
    for (int i = 0; i < 4; i++)
        #pragma unroll
        for (int j = 0; j < 4; j++) acc[i][j] = 0.f;

    for (int kb = 0; kb < 256; kb += 16) {
        {
            int m = tid >> 2, q = tid & 3;
            float4 av = *(const float4*)(A + (size_t)(tm+m)*256 + kb + q*4);
            As[q*4+0][m]=av.x; As[q*4+1][m]=av.y; As[q*4+2][m]=av.z; As[q*4+3][m]=av.w;
        }
        if (!bT) {
            int r = tid >> 4, c4 = (tid & 15)*4;
            float4 bv = *(const float4*)(Bm + (size_t)(kb+r)*256 + tn + c4);
            *(float4*)&Bs[r][c4] = bv;
        } else {
            int nn = tid >> 2, q = tid & 3;
            float4 bv = *(const float4*)(Bm + (size_t)(tn+nn)*256 + kb + q*4);
            Bs[q*4+0][nn]=bv.x; Bs[q*4+1][nn]=bv.y; Bs[q*4+2][nn]=bv.z; Bs[q*4+3][nn]=bv.w;
        }
        __syncthreads();
        #pragma unroll
        for (int kk = 0; kk < 16; kk++) {
            float4 a4 = *(float4*)&As[kk][ty*4];
            float4 b4 = *(float4*)&Bs[kk][tx*4];
            float av[4] = {a4.x,a4.y,a4.z,a4.w};
            float bv[4] = {b4.x,b4.y,b4.z,b4.w};
            #pragma unroll
            for (int i = 0; i < 4; i++)
                #pragma unroll
                for (int j = 0; j < 4; j++) acc[i][j] += av[i]*bv[j];
        }
        __syncthreads();
    }
    #pragma unroll
    for (int i = 0; i < 4; i++) {
        int r = tm + ty*4 + i;
        #pragma unroll
        for (int j = 0; j < 4; j++) {
            int c = tn + tx*4 + j;
            float v = acc[i][j];
            if (bias) v += bias[c];
            if (ep == 1) {
                v += add1[(size_t)r*256 + c] + add2[(r>>9)*256 + c];
                C[(size_t)r*256 + c] = v;
            } else if (ep == 2) {
                v = v > 0.f ? v : 0.01f*v;
                C[(size_t)r*256 + c] += v;
            } else if (ep == 3) {
                int orow = (r>>9)*LP1 + (r & 511) + 1;
                C[(size_t)orow*256 + c] = v;
            } else {
                C[(size_t)r*256 + c] = v;
            }
        }
    }
}

// ------- fused GAT attention + output proj epilogue -------
// grid (NH*B, 4), block 256 (8 warps × 16 rows each), dyn smem 67584B
__global__ void k_gat_attn(const float* __restrict__ fcb) {
    extern __shared__ float sm[];
    float* sg  = sm;              // [512][32]
    float* sej = sm + L*HD;       // [512]
    int n = blockIdx.x & 7, b = blockIdx.x >> 3;
    int i0 = blockIdx.y * 128;
    int tid = threadIdx.x, lane = tid & 31, w = tid >> 5;

    const float* gb = g_gbuf + ((size_t)b*L)*ND + n*HD;
    for (int idx = tid; idx < L*HD; idx += blockDim.x) {
        int j = idx >> 5, d = idx & 31;
        sg[idx] = gb[(size_t)j*ND + d];
    }
    for (int idx = tid; idx < L; idx += blockDim.x)
        sej[idx] = g_ej[n*BL + b*L + idx];
    __syncthreads();

    const float NEGINF = -1e30f;
    for (int rr = 0; rr < 16; rr++) {
        int i = i0 + w*16 + rr;
        float eii = g_ei[n*BL + b*L + i];
        const unsigned* arow = g_adj + ((size_t)b*L + i)*LW;
        unsigned words[LW];
        #pragma unroll
        for (int t = 0; t < LW; t++) words[t] = arow[t];

        float mx = NEGINF;
        #pragma unroll
        for (int t = 0; t < LW; t++)
            if ((words[t] >> lane) & 1u) mx = fmaxf(mx, sej[t*32 + lane]);
        mx = warp_max(mx);

        float acc = 0.f, den = 0.f;
        if (mx <= 0.5f*NEGINF) {
            // degenerate (no edges): reference softmax becomes uniform over all j
            for (int j = 0; j < L; j++) acc += sg[j*HD + lane];
            den = (float)L;
        } else {
            float M = eii + mx;
            M = M > 0.f ? M : 0.2f*M;
            #pragma unroll
            for (int t = 0; t < LW; t++) {
                float s = eii + sej[t*32 + lane];
                s = s > 0.f ? s : 0.2f*s;
                float wgt = ((words[t] >> lane) & 1u) ? __expf(s - M) : 0.f;
                den += wgt;
                #pragma unroll
                for (int kk = 0; kk < 32; kk++) {
                    float wv = __shfl_sync(0xffffffffu, wgt, kk);
                    acc += wv * sg[(t*32 + kk)*HD + lane];
                }
            }
            den = warp_sum(den);
        }
        float o = acc/den + fcb[n*HD + lane];
        o = o > 0.f ? o : expm1f(o);            // elu
        g_temp[((size_t)b*L + i)*ND + n*HD + lane] = o;
    }
}

// star-attn row 0 of kproj: relay @ sk_w^T + sk_b
__global__ void k_kproj0(const float* __restrict__ skw, const float* __restrict__ skb) {
    int b = blockIdx.x, c = threadIdx.x;
    __shared__ float sr[H];
    sr[c] = g_relay[b*H + c];
    __syncthreads();
    float s = skb[c];
    for (int h = 0; h < H; h++) s += sr[h]*skw[(size_t)c*H + h];
    g_kproj[(size_t)b*LP1*ND + c] = s;
}

// fused star attention: grid B, 256 threads (warp per head)
__global__ void k_star(const int* __restrict__ mask) {
    __shared__ float spre[NH][LP1 + 7];
    int b = blockIdx.x, tid = threadIdx.x, n = tid >> 5, lane = tid & 31;
    float qv = g_qproj[b*ND + n*HD + lane];
    const float scale = 0.17677669529663689f;   // 1/sqrt(32)
    const float* kp = g_kproj + (size_t)b*LP1*ND + n*HD;
    for (int l = 0; l < LP1; l++) {
        float p = qv * kp[(size_t)l*ND + lane];
        p = warp_sum(p);
        if (lane == 0) spre[n][l] = p*scale;
    }
    __syncwarp();
    float mx = -1e30f;
    for (int l = lane; l < LP1; l += 32) {
        bool valid = (l == 0) || (mask[b*L + l - 1] != 0);
        if (valid) mx = fmaxf(mx, spre[n][l]);
    }
    mx = warp_max(mx);
    float sum = 0.f;
    for (int l = lane; l < LP1; l += 32) {
        bool valid = (l == 0) || (mask[b*L + l - 1] != 0);
        float wv = valid ? __expf(spre[n][l] - mx) : 0.f;
        spre[n][l] = wv;
        sum += wv;
    }
    sum = warp_sum(sum);
    __syncwarp();
    float acc = 0.f;
    for (int l = 0; l < LP1; l++) acc += spre[n][l] * kp[(size_t)l*ND + lane];
    g_attv[b*ND + n*HD + lane] = acc / sum;
}

// relay = lrelu(attv @ so_w^T + so_b, 0.01)
__global__ void k_so(const float* __restrict__ sow, const float* __restrict__ sob) {
    int b = blockIdx.x, h = threadIdx.x;
    __shared__ float sa[ND];
    sa[h] = g_attv[b*ND + h];
    __syncthreads();
    float s = sob[h];
    for (int c = 0; c < ND; c++) s += sa[c]*sow[(size_t)h*ND + c];
    g_relay[b*H + h] = s > 0.f ? s : 0.01f*s;
}

__global__ void k_zeropad(const int* __restrict__ mask) {
    int idx = blockIdx.x*blockDim.x + threadIdx.x;
    if (idx >= BL*H) return;
    if (mask[idx >> 8] == 0) g_nodes[idx] = 0.f;
}

__global__ void k_out(float* __restrict__ out, int total) {
    int idx = blockIdx.x*blockDim.x + threadIdx.x;
    if (idx >= total) return;
    out[idx] = (idx < BL*H) ? g_nodes[idx] : g_relay[idx - BL*H];
}

// ---------------- launch ----------------
extern "C" void kernel_launch(void* const* d_in, const int* in_sizes, int n_in,
                              void* d_out, int out_size) {
    const float* data    = (const float*)d_in[0];
    const float* WQw     = (const float*)d_in[1];
    const float* WQb     = (const float*)d_in[2];
    const float* a1      = (const float*)d_in[3];
    const float* a2      = (const float*)d_in[4];
    const float* fcw_gat = (const float*)d_in[5];
    const float* fcb_gat = (const float*)d_in[6];
    const float* norm_g  = (const float*)d_in[7];
    const float* norm_b  = (const float*)d_in[8];
    const float* sq_w    = (const float*)d_in[9];
    const float* sq_b    = (const float*)d_in[10];
    const float* sk_w    = (const float*)d_in[11];
    const float* sk_b    = (const float*)d_in[12];
    const float* so_w    = (const float*)d_in[13];
    const float* so_b    = (const float*)d_in[14];
    const float* fc_w    = (const float*)d_in[15];
    const float* fc_b    = (const float*)d_in[16];
    const int*   mask    = (const int*)d_in[17];
    const int*   edge    = (const int*)d_in[18];
    float* out = (float*)d_out;

    const int GAT_SMEM = (L*HD + L) * (int)sizeof(float);   // 67584
    cudaFuncSetAttribute(k_gat_attn, cudaFuncAttributeMaxDynamicSharedMemorySize, GAT_SMEM);

    float *p_nodes, *p_xn, *p_gdat, *p_gbuf, *p_temp, *p_Mcat, *p_Gw, *p_bqF, *p_grel, *p_kproj;
    cudaGetSymbolAddress((void**)&p_nodes, g_nodes);
    cudaGetSymbolAddress((void**)&p_xn,    g_xn);
    cudaGetSymbolAddress((void**)&p_gdat,  g_gdat);
    cudaGetSymbolAddress((void**)&p_gbuf,  g_gbuf);
    cudaGetSymbolAddress((void**)&p_temp,  g_temp);
    cudaGetSymbolAddress((void**)&p_Mcat,  g_Mcat);
    cudaGetSymbolAddress((void**)&p_Gw,    g_Gw);
    cudaGetSymbolAddress((void**)&p_bqF,   g_bqF);
    cudaGetSymbolAddress((void**)&p_grel,  g_grel);
    cudaGetSymbolAddress((void**)&p_kproj, g_kproj);

    cudaMemcpyAsync(p_nodes, data, sizeof(float)*BL*H, cudaMemcpyDeviceToDevice);

    k_pack_adj<<<1024, 256>>>(edge);
    k_relay0<<<B, 256>>>(data);
    k_prep_wa<<<NH, 256>>>(WQw, WQb, a1, a2);
    k_prep_bqF<<<NH, 32>>>(WQb, fcw_gat);
    k_prep_GH<<<(H*ND + 255)/256, 256>>>(fcw_gat);
    k_prep_Mcat<<<NH, 256>>>(WQw, fcw_gat);
    k_d12<<<1024, 256>>>(data, a1, a2);
    // gdat = data @ Gw
    k_gemm256<<<dim3(128,4), 256>>>(data, p_Gw, p_gdat, 0, 0, nullptr, nullptr, nullptr);

    for (int i = 0; i < ITR; i++) {
        k_ln<<<1024, 256>>>(norm_g + i*H, norm_b + i*H);
        k_relay_small<<<B, 256>>>(a1, a2, sq_w + (size_t)i*ND*H, sq_b + i*ND);
        k_eij<<<1024, 256>>>();
        // g = xn @ Mcat + bqF + gdat + grel
        k_gemm256<<<dim3(128,4), 256>>>(p_xn, p_Mcat, p_gbuf, 0, 1, p_bqF, p_gdat, p_grel);
        k_gat_attn<<<dim3(NH*B, 4), 256, GAT_SMEM>>>(fcb_gat);
        // nodes += lrelu(temp @ fc_w + fc_b)
        k_gemm256<<<dim3(128,4), 256>>>(p_temp, fc_w, p_nodes, 0, 2, fc_b, nullptr, nullptr);
        // star attention
        k_kproj0<<<B, 256>>>(sk_w + (size_t)i*ND*H, sk_b + i*ND);
        k_gemm256<<<dim3(128,4), 256>>>(p_nodes, sk_w + (size_t)i*ND*H, p_kproj, 1, 3,
                                        sk_b + i*ND, nullptr, nullptr);
        k_star<<<B, 256>>>(mask);
        k_so<<<B, 256>>>(so_w + (size_t)i*H*ND, so_b + i*H);
        k_zeropad<<<(BL*H + 255)/256, 256>>>(mask);
    }

    int total = BL*H + B*H;
    if (total > out_size) total = out_size;
    k_out<<<(total + 255)/256, 256>>>(out, total);
}

// round 4
// speedup vs baseline: 1.4982x; 1.4982x over previous
#include <cuda_runtime.h>
#include <math.h>

#define B   16
#define L   512
#define H   256
#define NH  8
#define HD  32
#define ND  256        // NH*HD
#define ITR 2
#define BL  (B*L)      // 8192
#define LP1 (L+1)      // 513
#define LW  (L/32)     // 16 adjacency words per row

// ---------------- device scratch (no allocs allowed) ----------------
__device__ float    g_nodes[BL*H];
__device__ float    g_xn[BL*H];
__device__ float    g_relay[B*H];
__device__ float    g_d1[NH*BL];
__device__ float    g_d2[NH*BL];
__device__ float    g_ei[NH*BL];
__device__ float    g_ej[NH*BL];
__device__ float    g_gdat[BL*ND];
__device__ float    g_gbuf[BL*ND];
__device__ float    g_temp[BL*ND];
__device__ float    g_wa1[NH*H];
__device__ float    g_wa2[NH*H];
__device__ float    g_c1[NH];
__device__ float    g_c2[NH];
__device__ float    g_bqF[ND];
__device__ float    g_Mcat[H*ND];
__device__ float    g_Gw[H*ND];
__device__ float    g_Hw[H*ND];
__device__ unsigned g_adj[BL*LW];
__device__ float    g_r1[NH*B];
__device__ float    g_r2[NH*B];
__device__ float    g_grel[B*ND];
__device__ float    g_kproj[B*LP1*ND];
__device__ float    g_qproj[B*ND];
__device__ float    g_attv[B*ND];

__device__ __forceinline__ float warp_sum(float v) {
    #pragma unroll
    for (int o = 16; o; o >>= 1) v += __shfl_xor_sync(0xffffffffu, v, o);
    return v;
}
__device__ __forceinline__ float warp_max(float v) {
    #pragma unroll
    for (int o = 16; o; o >>= 1) v = fmaxf(v, __shfl_xor_sync(0xffffffffu, v, o));
    return v;
}
__device__ __forceinline__ unsigned f2tf(float f) {
    unsigned u; asm("cvt.rna.tf32.f32 %0, %1;" : "=r"(u) : "f"(f)); return u;
}
__device__ __forceinline__ void mma8(float* c, const unsigned* a, const unsigned* b) {
    asm volatile("mma.sync.aligned.m16n8k8.row.col.f32.tf32.tf32.f32 "
        "{%0,%1,%2,%3}, {%4,%5,%6,%7}, {%8,%9}, {%0,%1,%2,%3};"
        : "+f"(c[0]), "+f"(c[1]), "+f"(c[2]), "+f"(c[3])
        : "r"(a[0]), "r"(a[1]), "r"(a[2]), "r"(a[3]), "r"(b[0]), "r"(b[1]));
}

// ---------------- one-time-per-launch prep ----------------

__global__ void k_pack_adj(const int* __restrict__ edge) {
    int warp = (blockIdx.x * blockDim.x + threadIdx.x) >> 5;
    int lane = threadIdx.x & 31;
    if (warp >= BL) return;
    const int* row = edge + (size_t)warp * L;
    #pragma unroll
    for (int t = 0; t < LW; t++) {
        unsigned m = __ballot_sync(0xffffffffu, row[t*32 + lane] > 0);
        if (lane == 0) g_adj[warp*LW + t] = m;
    }
}

__global__ void k_relay0(const float* __restrict__ data) {
    int b = blockIdx.x, h = threadIdx.x;
    float s = 0.f;
    #pragma unroll 8
    for (int l = 0; l < L; l++) s += data[((size_t)b*L + l)*H + h];
    g_relay[b*H + h] = s * (1.0f/L);
}

__global__ void k_prep_wa(const float* __restrict__ Wq, const float* __restrict__ bq,
                          const float* __restrict__ a1, const float* __restrict__ a2) {
    int n = blockIdx.x, m = threadIdx.x;
    const float* W  = Wq + (size_t)n*H*H;
    const float* A1 = a1 + n*3*H;
    const float* A2 = a2 + n*3*H;
    float s1 = 0.f, s2 = 0.f;
    #pragma unroll 8
    for (int k = 0; k < H; k++) { float w = W[k*H + m]; s1 += A1[k]*w; s2 += A2[k]*w; }
    g_wa1[n*H + m] = s1; g_wa2[n*H + m] = s2;
    if (m == 0) {
        float c1 = 0.f, c2 = 0.f;
        for (int k = 0; k < H; k++) { c1 += A1[k]*bq[n*H + k]; c2 += A2[k]*bq[n*H + k]; }
        g_c1[n] = c1; g_c2[n] = c2;
    }
}

// bqF: block per head, k split across 8 warps
__global__ void k_prep_bqF(const float* __restrict__ bq, const float* __restrict__ fcw) {
    __shared__ float red[8][HD];
    int n = blockIdx.x, t = threadIdx.x, d = t & 31, kw = t >> 5;
    float s = 0.f;
    #pragma unroll
    for (int q = 0; q < 32; q++) {
        int k = kw*32 + q;
        s += bq[n*H + k] * fcw[((size_t)n*3*H + k)*HD + d];
    }
    red[kw][d] = s;
    __syncthreads();
    if (kw == 0) {
        float a = 0.f;
        #pragma unroll
        for (int u = 0; u < 8; u++) a += red[u][d];
        g_bqF[n*HD + d] = a;
    }
}

__global__ void k_prep_GH(const float* __restrict__ fcw) {
    int idx = blockIdx.x*blockDim.x + threadIdx.x;
    if (idx >= H*ND) return;
    int k = idx >> 8, c = idx & 255, n = c >> 5, d = c & 31;
    g_Gw[idx] = fcw[((size_t)n*3*H + (H + 2*k    ))*HD + d];
    g_Hw[idx] = fcw[((size_t)n*3*H + (H + 2*k + 1))*HD + d];
}

// Mcat: grid (NH,2) — k split, atomicAdd into zeroed g_Mcat
__global__ void k_prep_Mcat(const float* __restrict__ Wq, const float* __restrict__ fcw) {
    __shared__ float sF[128*HD];             // 16KB half of Fw_top
    int n = blockIdx.x, half = blockIdx.y, m = threadIdx.x;
    int k0 = half * 128;
    for (int i = m; i < 128*HD; i += blockDim.x)
        sF[i] = fcw[(size_t)n*3*H*HD + (size_t)k0*HD + i];
    __syncthreads();
    float acc[HD];
    #pragma unroll
    for (int d = 0; d < HD; d++) acc[d] = 0.f;
    const float* W = Wq + (size_t)n*H*H + (size_t)k0*H;
    for (int k = 0; k < 128; k++) {
        float w = W[k*H + m];
        #pragma unroll
        for (int d = 0; d < HD; d++) acc[d] += w * sF[k*HD + d];
    }
    #pragma unroll
    for (int d = 0; d < HD; d++) atomicAdd(&g_Mcat[m*ND + n*HD + d], acc[d]);
}

__global__ void k_d12(const float* __restrict__ data, const float* __restrict__ a1,
                      const float* __restrict__ a2) {
    int warp = (blockIdx.x*blockDim.x + threadIdx.x) >> 5, lane = threadIdx.x & 31;
    if (warp >= BL) return;
    float x[8];
    const float* row = data + (size_t)warp*H;
    #pragma unroll
    for (int t = 0; t < 8; t++) x[t] = row[t*32 + lane];
    for (int n = 0; n < NH; n++) {
        const float* A1 = a1 + n*3*H + H;
        const float* A2 = a2 + n*3*H + H;
        float s1 = 0.f, s2 = 0.f;
        #pragma unroll
        for (int t = 0; t < 8; t++) { int k = t*32+lane; s1 += x[t]*A1[2*k]; s2 += x[t]*A2[2*k]; }
        s1 = warp_sum(s1); s2 = warp_sum(s2);
        if (lane == 0) { g_d1[n*BL + warp] = s1; g_d2[n*BL + warp] = s2; }
    }
}

// ---------------- per-iteration kernels ----------------

__global__ void k_ln(const float* __restrict__ gamma, const float* __restrict__ beta) {
    int warp = (blockIdx.x*blockDim.x + threadIdx.x) >> 5, lane = threadIdx.x & 31;
    if (warp >= BL) return;
    float x[8];
    const float* row = g_nodes + (size_t)warp*H;
    float s = 0.f;
    #pragma unroll
    for (int t = 0; t < 8; t++) { x[t] = row[t*32 + lane]; s += x[t]; }
    s = warp_sum(s);
    float mean = s * (1.0f/H);
    float v = 0.f;
    #pragma unroll
    for (int t = 0; t < 8; t++) { float d = x[t]-mean; v += d*d; }
    v = warp_sum(v);
    float rstd = rsqrtf(v * (1.0f/H) + 1e-5f);
    #pragma unroll
    for (int t = 0; t < 8; t++) {
        int h = t*32 + lane;
        g_xn[(size_t)warp*H + h] = (x[t]-mean)*rstd*gamma[h] + beta[h];
    }
}

// relay-dependent small stuff: grid (B,2). y=0: grel + r1/r2; y=1: qproj (warp/output)
__global__ void k_relay_small(const float* __restrict__ a1, const float* __restrict__ a2,
                              const float* __restrict__ sqw, const float* __restrict__ sqb) {
    int b = blockIdx.x, t = threadIdx.x, lane = t & 31, w = t >> 5;
    __shared__ float sr[H];
    sr[t] = g_relay[b*H + t];
    __syncthreads();
    if (blockIdx.y == 0) {
        float s = 0.f;
        #pragma unroll 8
        for (int k = 0; k < H; k++) s += sr[k] * g_Hw[k*ND + t];
        g_grel[b*ND + t] = s;
        if (t < NH) {
            int n = t; float s1 = 0.f, s2 = 0.f;
            const float* A1 = a1 + n*3*H + H;
            const float* A2 = a2 + n*3*H + H;
            for (int k = 0; k < H; k++) { s1 += sr[k]*A1[2*k+1]; s2 += sr[k]*A2[2*k+1]; }
            g_r1[n*B + b] = s1; g_r2[n*B + b] = s2;
        }
    } else {
        // qproj: each warp computes 32 outputs with coalesced weight rows
        for (int o = 0; o < 32; o++) {
            int c = w*32 + o;
            float acc = 0.f;
            #pragma unroll
            for (int q = 0; q < 8; q++)
                acc += sr[q*32 + lane] * sqw[(size_t)c*H + q*32 + lane];
            acc = warp_sum(acc);
            if (lane == 0) g_qproj[b*ND + c] = acc + sqb[c];
        }
    }
}

__global__ void k_eij() {
    int warp = (blockIdx.x*blockDim.x + threadIdx.x) >> 5, lane = threadIdx.x & 31;
    if (warp >= BL) return;
    int b = warp >> 9;
    float x[8];
    const float* row = g_xn + (size_t)warp*H;
    #pragma unroll
    for (int t = 0; t < 8; t++) x[t] = row[t*32 + lane];
    for (int n = 0; n < NH; n++) {
        float s1 = 0.f, s2 = 0.f;
        #pragma unroll
        for (int t = 0; t < 8; t++) {
            int k = t*32+lane;
            s1 += x[t]*g_wa1[n*H + k];
            s2 += x[t]*g_wa2[n*H + k];
        }
        s1 = warp_sum(s1); s2 = warp_sum(s2);
        if (lane == 0) {
            g_ei[n*BL + warp] = s1 + g_d1[n*BL + warp] + g_r1[n*B + b] + g_c1[n];
            g_ej[n*BL + warp] = s2 + g_d2[n*BL + warp] + g_r2[n*B + b] + g_c2[n];
        }
    }
}

// ------- tf32 tensor-core GEMM: M tile 128, N tile 64, K=256, 8 warps -------
// ep: 0 = C=acc(+bias)   1 = +bias+add1[r]+add2[b]   2 = C += lrelu(acc+bias,0.01)
//     3 = kproj remap row (b*513 + l + 1), C=acc+bias
__global__ __launch_bounds__(256) void k_gemm_tf32(
        const float* __restrict__ A, const float* __restrict__ Bm,
        float* __restrict__ C, int bT, int ep,
        const float* __restrict__ bias,
        const float* __restrict__ add1, const float* __restrict__ add2) {
    __shared__ unsigned As[128][36];   // K-chunk 32 + pad 4
    __shared__ unsigned Bs[32][72];    // N 64 + pad 8
    int tid = threadIdx.x;
    int warp = tid >> 5, lane = tid & 31;
    int wm = warp >> 1, wn = warp & 1;          // 4 x 2 warp grid
    int g = lane >> 2, tig = lane & 3;
    int tm = blockIdx.x * 128, tn = blockIdx.y * 64;

    float c[2][4][4];
    #pragma unroll
    for (int mt = 0; mt < 2; mt++)
        #pragma unroll
        for (int nt = 0; nt < 4; nt++)
            #pragma unroll
            for (int i = 0; i < 4; i++) c[mt][nt][i] = 0.f;

    for (int kb = 0; kb < 256; kb += 32) {
        #pragma unroll
        for (int j = 0; j < 4; j++) {
            int idx = tid + 256*j;
            int r = idx >> 3, c4 = (idx & 7) * 4;
            float4 v = *(const float4*)(A + (size_t)(tm + r)*256 + kb + c4);
            As[r][c4+0] = f2tf(v.x); As[r][c4+1] = f2tf(v.y);
            As[r][c4+2] = f2tf(v.z); As[r][c4+3] = f2tf(v.w);
        }
        if (!bT) {
            #pragma unroll
            for (int j = 0; j < 2; j++) {
                int idx = tid + 256*j;
                int r = idx >> 4, c4 = (idx & 15) * 4;
                float4 v = *(const float4*)(Bm + (size_t)(kb + r)*256 + tn + c4);
                Bs[r][c4+0] = f2tf(v.x); Bs[r][c4+1] = f2tf(v.y);
                Bs[r][c4+2] = f2tf(v.z); Bs[r][c4+3] = f2tf(v.w);
            }
        } else {
            #pragma unroll
            for (int j = 0; j < 2; j++) {
                int idx = tid + 256*j;
                int cc = idx & 63, q = idx >> 6;   // q in 0..7 -> k rows q*4..q*4+3
                float4 v = *(const float4*)(Bm + (size_t)(tn + cc)*256 + kb + q*4);
                Bs[q*4+0][cc] = f2tf(v.x); Bs[q*4+1][cc] = f2tf(v.y);
                Bs[q*4+2][cc] = f2tf(v.z); Bs[q*4+3][cc] = f2tf(v.w);
            }
        }
        __syncthreads();
        #pragma unroll
        for (int ks = 0; ks < 32; ks += 8) {
            unsigned af[2][4], bf[4][2];
            #pragma unroll
            for (int mt = 0; mt < 2; mt++) {
                int R = wm*32 + mt*16;
                af[mt][0] = As[R+g  ][ks+tig  ];
                af[mt][1] = As[R+g+8][ks+tig  ];
                af[mt][2] = As[R+g  ][ks+tig+4];
                af[mt][3] = As[R+g+8][ks+tig+4];
            }
            #pragma unroll
            for (int nt = 0; nt < 4; nt++) {
                int Cn = wn*32 + nt*8;
                bf[nt][0] = Bs[ks+tig  ][Cn+g];
                bf[nt][1] = Bs[ks+tig+4][Cn+g];
            }
            #pragma unroll
            for (int mt = 0; mt < 2; mt++)
                #pragma unroll
                for (int nt = 0; nt < 4; nt++)
                    mma8(c[mt][nt], af[mt], bf[nt]);
        }
        __syncthreads();
    }
    // epilogue
    #pragma unroll
    for (int mt = 0; mt < 2; mt++) {
        #pragma unroll
        for (int nt = 0; nt < 4; nt++) {
            #pragma unroll
            for (int half = 0; half < 2; half++) {
                int r = tm + wm*32 + mt*16 + g + half*8;
                int col = tn + wn*32 + nt*8 + tig*2;
                float v0 = c[mt][nt][half*2+0];
                float v1 = c[mt][nt][half*2+1];
                if (bias) { v0 += bias[col]; v1 += bias[col+1]; }
                if (ep == 1) {
                    v0 += add1[(size_t)r*256 + col]   + add2[(r>>9)*256 + col];
                    v1 += add1[(size_t)r*256 + col+1] + add2[(r>>9)*256 + col+1];
                    float2 o = {v0, v1};
                    *(float2*)(C + (size_t)r*256 + col) = o;
                } else if (ep == 2) {
                    v0 = v0 > 0.f ? v0 : 0.01f*v0;
                    v1 = v1 > 0.f ? v1 : 0.01f*v1;
                    float2 old = *(float2*)(C + (size_t)r*256 + col);
                    float2 o = {old.x + v0, old.y + v1};
                    *(float2*)(C + (size_t)r*256 + col) = o;
                } else if (ep == 3) {
                    int orow = (r>>9)*LP1 + (r & 511) + 1;
                    float2 o = {v0, v1};
                    *(float2*)(C + (size_t)orow*256 + col) = o;
                } else {
                    float2 o = {v0, v1};
                    *(float2*)(C + (size_t)r*256 + col) = o;
                }
            }
        }
    }
}

// ------- fused GAT attention (unchanged this round) -------
__global__ void k_gat_attn(const float* __restrict__ fcb) {
    extern __shared__ float sm[];
    float* sg  = sm;              // [512][32]
    float* sej = sm + L*HD;       // [512]
    int n = blockIdx.x & 7, b = blockIdx.x >> 3;
    int i0 = blockIdx.y * 128;
    int tid = threadIdx.x, lane = tid & 31, w = tid >> 5;

    const float* gb = g_gbuf + ((size_t)b*L)*ND + n*HD;
    for (int idx = tid; idx < L*HD; idx += blockDim.x) {
        int j = idx >> 5, d = idx & 31;
        sg[idx] = gb[(size_t)j*ND + d];
    }
    for (int idx = tid; idx < L; idx += blockDim.x)
        sej[idx] = g_ej[n*BL + b*L + idx];
    __syncthreads();

    const float NEGINF = -1e30f;
    for (int rr = 0; rr < 16; rr++) {
        int i = i0 + w*16 + rr;
        float eii = g_ei[n*BL + b*L + i];
        const unsigned* arow = g_adj + ((size_t)b*L + i)*LW;
        unsigned words[LW];
        #pragma unroll
        for (int t = 0; t < LW; t++) words[t] = arow[t];

        float mx = NEGINF;
        #pragma unroll
        for (int t = 0; t < LW; t++)
            if ((words[t] >> lane) & 1u) mx = fmaxf(mx, sej[t*32 + lane]);
        mx = warp_max(mx);

        float acc = 0.f, den = 0.f;
        if (mx <= 0.5f*NEGINF) {
            for (int j = 0; j < L; j++) acc += sg[j*HD + lane];
            den = (float)L;
        } else {
            float M = eii + mx;
            M = M > 0.f ? M : 0.2f*M;
            #pragma unroll
            for (int t = 0; t < LW; t++) {
                float s = eii + sej[t*32 + lane];
                s = s > 0.f ? s : 0.2f*s;
                float wgt = ((words[t] >> lane) & 1u) ? __expf(s - M) : 0.f;
                den += wgt;
                #pragma unroll
                for (int kk = 0; kk < 32; kk++) {
                    float wv = __shfl_sync(0xffffffffu, wgt, kk);
                    acc += wv * sg[(t*32 + kk)*HD + lane];
                }
            }
            den = warp_sum(den);
        }
        float o = acc/den + fcb[n*HD + lane];
        o = o > 0.f ? o : expm1f(o);            // elu
        g_temp[((size_t)b*L + i)*ND + n*HD + lane] = o;
    }
}

// star-attn row 0 of kproj: relay @ sk_w^T + sk_b  (warp-per-output)
__global__ void k_kproj0(const float* __restrict__ skw, const float* __restrict__ skb) {
    int b = blockIdx.x, t = threadIdx.x, lane = t & 31, w = t >> 5;
    __shared__ float sr[H];
    sr[t] = g_relay[b*H + t];
    __syncthreads();
    for (int o = 0; o < 32; o++) {
        int c = w*32 + o;
        float acc = 0.f;
        #pragma unroll
        for (int q = 0; q < 8; q++)
            acc += sr[q*32 + lane] * skw[(size_t)c*H + q*32 + lane];
        acc = warp_sum(acc);
        if (lane == 0) g_kproj[(size_t)b*LP1*ND + c] = acc + skb[c];
    }
}

// fused star attention: grid (B, NH), 256 threads
__global__ void k_star(const int* __restrict__ mask) {
    __shared__ float sq[HD];
    __shared__ float sw[LP1];
    __shared__ float redm[8];
    __shared__ float reds[8];
    __shared__ float part[8][HD];
    int b = blockIdx.x, n = blockIdx.y;
    int tid = threadIdx.x, lane = tid & 31, w = tid >> 5;
    if (tid < HD) sq[tid] = g_qproj[b*ND + n*HD + tid];
    __syncthreads();
    const float scale = 0.17677669529663689f;   // 1/sqrt(32)
    const float* kp = g_kproj + (size_t)b*LP1*ND + n*HD;
    for (int l = tid; l < LP1; l += 256) {
        bool valid = (l == 0) || (mask[b*L + l - 1] != 0);
        float s = -1e30f;
        if (valid) {
            const float4* row = (const float4*)(kp + (size_t)l*ND);
            float acc = 0.f;
            #pragma unroll
            for (int q = 0; q < 8; q++) {
                float4 v = row[q];
                acc += v.x*sq[q*4+0] + v.y*sq[q*4+1] + v.z*sq[q*4+2] + v.w*sq[q*4+3];
            }
            s = acc * scale;
        }
        sw[l] = s;
    }
    __syncthreads();
    float mx = -1e30f;
    for (int l = tid; l < LP1; l += 256) mx = fmaxf(mx, sw[l]);
    mx = warp_max(mx);
    if (lane == 0) redm[w] = mx;
    __syncthreads();
    if (w == 0) {
        float v = (lane < 8) ? redm[lane] : -1e30f;
        v = warp_max(v);
        if (lane == 0) redm[0] = v;
    }
    __syncthreads();
    mx = redm[0];
    float sum = 0.f;
    for (int l = tid; l < LP1; l += 256) {
        float e = __expf(sw[l] - mx);
        sw[l] = e;
        sum += e;
    }
    sum = warp_sum(sum);
    if (lane == 0) reds[w] = sum;
    __syncthreads();
    float total = 0.f;
    #pragma unroll
    for (int u = 0; u < 8; u++) total += reds[u];
    float inv = 1.0f / total;
    float acc = 0.f;
    for (int l = w; l < LP1; l += 8)
        acc += sw[l] * kp[(size_t)l*ND + lane];
    part[w][lane] = acc;
    __syncthreads();
    if (w == 0) {
        float a = 0.f;
        #pragma unroll
        for (int u = 0; u < 8; u++) a += part[u][lane];
        g_attv[b*ND + n*HD + lane] = a * inv;
    }
}

// relay = lrelu(attv @ so_w^T + so_b, 0.01)  (warp-per-output)
__global__ void k_so(const float* __restrict__ sow, const float* __restrict__ sob) {
    int b = blockIdx.x, t = threadIdx.x, lane = t & 31, w = t >> 5;
    __shared__ float sa[ND];
    sa[t] = g_attv[b*ND + t];
    __syncthreads();
    for (int o = 0; o < 32; o++) {
        int h = w*32 + o;
        float acc = 0.f;
        #pragma unroll
        for (int q = 0; q < 8; q++)
            acc += sa[q*32 + lane] * sow[(size_t)h*ND + q*32 + lane];
        acc = warp_sum(acc);
        if (lane == 0) {
            float s = acc + sob[h];
            g_relay[b*H + h] = s > 0.f ? s : 0.01f*s;
        }
    }
}

__global__ void k_zeropad(const int* __restrict__ mask) {
    int idx = blockIdx.x*blockDim.x + threadIdx.x;
    if (idx >= BL*H) return;
    if (mask[idx >> 8] == 0) g_nodes[idx] = 0.f;
}

__global__ void k_out(float* __restrict__ out, int total) {
    int idx = blockIdx.x*blockDim.x + threadIdx.x;
    if (idx >= total) return;
    out[idx] = (idx < BL*H) ? g_nodes[idx] : g_relay[idx - BL*H];
}

// ---------------- launch ----------------
extern "C" void kernel_launch(void* const* d_in, const int* in_sizes, int n_in,
                              void* d_out, int out_size) {
    const float* data    = (const float*)d_in[0];
    const float* WQw     = (const float*)d_in[1];
    const float* WQb     = (const float*)d_in[2];
    const float* a1      = (const float*)d_in[3];
    const float* a2      = (const float*)d_in[4];
    const float* fcw_gat = (const float*)d_in[5];
    const float* fcb_gat = (const float*)d_in[6];
    const float* norm_g  = (const float*)d_in[7];
    const float* norm_b  = (const float*)d_in[8];
    const float* sq_w    = (const float*)d_in[9];
    const float* sq_b    = (const float*)d_in[10];
    const float* sk_w    = (const float*)d_in[11];
    const float* sk_b    = (const float*)d_in[12];
    const float* so_w    = (const float*)d_in[13];
    const float* so_b    = (const float*)d_in[14];
    const float* fc_w    = (const float*)d_in[15];
    const float* fc_b    = (const float*)d_in[16];
    const int*   mask    = (const int*)d_in[17];
    const int*   edge    = (const int*)d_in[18];
    float* out = (float*)d_out;

    const int GAT_SMEM = (L*HD + L) * (int)sizeof(float);   // 67584
    cudaFuncSetAttribute(k_gat_attn, cudaFuncAttributeMaxDynamicSharedMemorySize, GAT_SMEM);

    float *p_nodes, *p_xn, *p_gdat, *p_gbuf, *p_temp, *p_Mcat, *p_Gw, *p_bqF, *p_grel, *p_kproj;
    cudaGetSymbolAddress((void**)&p_nodes, g_nodes);
    cudaGetSymbolAddress((void**)&p_xn,    g_xn);
    cudaGetSymbolAddress((void**)&p_gdat,  g_gdat);
    cudaGetSymbolAddress((void**)&p_gbuf,  g_gbuf);
    cudaGetSymbolAddress((void**)&p_temp,  g_temp);
    cudaGetSymbolAddress((void**)&p_Mcat,  g_Mcat);
    cudaGetSymbolAddress((void**)&p_Gw,    g_Gw);
    cudaGetSymbolAddress((void**)&p_bqF,   g_bqF);
    cudaGetSymbolAddress((void**)&p_grel,  g_grel);
    cudaGetSymbolAddress((void**)&p_kproj, g_kproj);

    cudaMemcpyAsync(p_nodes, data, sizeof(float)*BL*H, cudaMemcpyDeviceToDevice);
    cudaMemsetAsync(p_Mcat, 0, sizeof(float)*H*ND);

    k_pack_adj<<<1024, 256>>>(edge);
    k_relay0<<<B, 256>>>(data);
    k_prep_wa<<<NH, 256>>>(WQw, WQb, a1, a2);
    k_prep_bqF<<<NH, 256>>>(WQb, fcw_gat);
    k_prep_GH<<<(H*ND + 255)/256, 256>>>(fcw_gat);
    k_prep_Mcat<<<dim3(NH, 2), 256>>>(WQw, fcw_gat);
    k_d12<<<1024, 256>>>(data, a1, a2);
    // gdat = data @ Gw
    k_gemm_tf32<<<dim3(64, 4), 256>>>(data, p_Gw, p_gdat, 0, 0, nullptr, nullptr, nullptr);

    for (int i = 0; i < ITR; i++) {
        k_ln<<<1024, 256>>>(norm_g + i*H, norm_b + i*H);
        k_relay_small<<<dim3(B, 2), 256>>>(a1, a2, sq_w + (size_t)i*ND*H, sq_b + i*ND);
        k_eij<<<1024, 256>>>();
        // g = xn @ Mcat + bqF + gdat + grel
        k_gemm_tf32<<<dim3(64, 4), 256>>>(p_xn, p_Mcat, p_gbuf, 0, 1, p_bqF, p_gdat, p_grel);
        k_gat_attn<<<dim3(NH*B, 4), 256, GAT_SMEM>>>(fcb_gat);
        // nodes += lrelu(temp @ fc_w + fc_b)
        k_gemm_tf32<<<dim3(64, 4), 256>>>(p_temp, fc_w, p_nodes, 0, 2, fc_b, nullptr, nullptr);
        // star attention
        k_kproj0<<<B, 256>>>(sk_w + (size_t)i*ND*H, sk_b + i*ND);
        k_gemm_tf32<<<dim3(64, 4), 256>>>(p_nodes, sk_w + (size_t)i*ND*H, p_kproj, 1, 3,
                                          sk_b + i*ND, nullptr, nullptr);
        k_star<<<dim3(B, NH), 256>>>(mask);
        k_so<<<B, 256>>>(so_w + (size_t)i*H*ND, so_b + i*H);
        k_zeropad<<<(BL*H + 255)/256, 256>>>(mask);
    }

    int total = BL*H + B*H;
    if (total > out_size) total = out_size;
    k_out<<<(total + 255)/256, 256>>>(out, total);
}

// round 7
// speedup vs baseline: 2.4003x; 1.6021x over previous
#include <cuda_runtime.h>
#include <math.h>

#define B   16
#define L   512
#define H   256
#define NH  8
#define HD  32
#define ND  256        // NH*HD
#define ITR 2
#define BL  (B*L)      // 8192
#define LP1 (L+1)      // 513
#define LW  (L/32)     // 16 adjacency words per row

// ---------------- device scratch (no allocs allowed) ----------------
__device__ float    g_nodes[BL*H];
__device__ float    g_xn[BL*H];
__device__ float    g_relay[B*H];
__device__ float    g_d1[NH*BL];
__device__ float    g_d2[NH*BL];
__device__ float    g_ei[NH*BL];
__device__ float    g_ej[NH*BL];
__device__ float    g_gdat[BL*ND];
__device__ float    g_gbuf[BL*ND];
__device__ float    g_temp[BL*ND];
__device__ float    g_wa1[NH*H];
__device__ float    g_wa2[NH*H];
__device__ float    g_c1[NH];
__device__ float    g_c2[NH];
__device__ float    g_bqF[ND];
__device__ float    g_Mcat[H*ND];
__device__ float    g_Gw[H*ND];
__device__ float    g_Hw[H*ND];
__device__ unsigned g_adj[BL*LW];
__device__ float    g_r1[NH*B];
__device__ float    g_r2[NH*B];
__device__ float    g_grel[B*ND];
__device__ float    g_kproj[B*LP1*ND];
__device__ float    g_qproj[B*ND];
__device__ float    g_attv[B*ND];

__device__ __forceinline__ float warp_sum(float v) {
    #pragma unroll
    for (int o = 16; o; o >>= 1) v += __shfl_xor_sync(0xffffffffu, v, o);
    return v;
}
__device__ __forceinline__ float warp_max(float v) {
    #pragma unroll
    for (int o = 16; o; o >>= 1) v = fmaxf(v, __shfl_xor_sync(0xffffffffu, v, o));
    return v;
}
__device__ __forceinline__ unsigned f2tf(float f) {
    unsigned u; asm("cvt.rna.tf32.f32 %0, %1;" : "=r"(u) : "f"(f)); return u;
}
__device__ __forceinline__ void mma8(float* c, const unsigned* a, const unsigned* b) {
    asm volatile("mma.sync.aligned.m16n8k8.row.col.f32.tf32.tf32.f32 "
        "{%0,%1,%2,%3}, {%4,%5,%6,%7}, {%8,%9}, {%0,%1,%2,%3};"
        : "+f"(c[0]), "+f"(c[1]), "+f"(c[2]), "+f"(c[3])
        : "r"(a[0]), "r"(a[1]), "r"(a[2]), "r"(a[3]), "r"(b[0]), "r"(b[1]));
}

// ---------------- one-time-per-launch prep ----------------

__global__ void k_pack_adj(const int* __restrict__ edge) {
    int warp = (blockIdx.x * blockDim.x + threadIdx.x) >> 5;
    int lane = threadIdx.x & 31;
    if (warp >= BL) return;
    const int* row = edge + (size_t)warp * L;
    #pragma unroll
    for (int t = 0; t < LW; t++) {
        unsigned m = __ballot_sync(0xffffffffu, row[t*32 + lane] > 0);
        if (lane == 0) g_adj[warp*LW + t] = m;
    }
}

__global__ void k_relay0(const float* __restrict__ data) {
    int b = blockIdx.x, h = threadIdx.x;
    float s = 0.f;
    #pragma unroll 8
    for (int l = 0; l < L; l++) s += data[((size_t)b*L + l)*H + h];
    g_relay[b*H + h] = s * (1.0f/L);
}

__global__ void k_prep_wa(const float* __restrict__ Wq, const float* __restrict__ bq,
                          const float* __restrict__ a1, const float* __restrict__ a2) {
    int n = blockIdx.x, m = threadIdx.x;
    const float* W  = Wq + (size_t)n*H*H;
    const float* A1 = a1 + n*3*H;
    const float* A2 = a2 + n*3*H;
    float s1 = 0.f, s2 = 0.f;
    #pragma unroll 8
    for (int k = 0; k < H; k++) { float w = W[k*H + m]; s1 += A1[k]*w; s2 += A2[k]*w; }
    g_wa1[n*H + m] = s1; g_wa2[n*H + m] = s2;
    if (m == 0) {
        float c1 = 0.f, c2 = 0.f;
        for (int k = 0; k < H; k++) { c1 += A1[k]*bq[n*H + k]; c2 += A2[k]*bq[n*H + k]; }
        g_c1[n] = c1; g_c2[n] = c2;
    }
}

__global__ void k_prep_bqF(const float* __restrict__ bq, const float* __restrict__ fcw) {
    __shared__ float red[8][HD];
    int n = blockIdx.x, t = threadIdx.x, d = t & 31, kw = t >> 5;
    float s = 0.f;
    #pragma unroll
    for (int q = 0; q < 32; q++) {
        int k = kw*32 + q;
        s += bq[n*H + k] * fcw[((size_t)n*3*H + k)*HD + d];
    }
    red[kw][d] = s;
    __syncthreads();
    if (kw == 0) {
        float a = 0.f;
        #pragma unroll
        for (int u = 0; u < 8; u++) a += red[u][d];
        g_bqF[n*HD + d] = a;
    }
}

__global__ void k_prep_GH(const float* __restrict__ fcw) {
    int idx = blockIdx.x*blockDim.x + threadIdx.x;
    if (idx >= H*ND) return;
    int k = idx >> 8, c = idx & 255, n = c >> 5, d = c & 31;
    g_Gw[idx] = fcw[((size_t)n*3*H + (H + 2*k    ))*HD + d];
    g_Hw[idx] = fcw[((size_t)n*3*H + (H + 2*k + 1))*HD + d];
}

__global__ void k_prep_Mcat(const float* __restrict__ Wq, const float* __restrict__ fcw) {
    __shared__ float sF[128*HD];
    int n = blockIdx.x, half = blockIdx.y, m = threadIdx.x;
    int k0 = half * 128;
    for (int i = m; i < 128*HD; i += blockDim.x)
        sF[i] = fcw[(size_t)n*3*H*HD + (size_t)k0*HD + i];
    __syncthreads();
    float acc[HD];
    #pragma unroll
    for (int d = 0; d < HD; d++) acc[d] = 0.f;
    const float* W = Wq + (size_t)n*H*H + (size_t)k0*H;
    for (int k = 0; k < 128; k++) {
        float w = W[k*H + m];
        #pragma unroll
        for (int d = 0; d < HD; d++) acc[d] += w * sF[k*HD + d];
    }
    #pragma unroll
    for (int d = 0; d < HD; d++) atomicAdd(&g_Mcat[m*ND + n*HD + d], acc[d]);
}

__global__ void k_d12(const float* __restrict__ data, const float* __restrict__ a1,
                      const float* __restrict__ a2) {
    int warp = (blockIdx.x*blockDim.x + threadIdx.x) >> 5, lane = threadIdx.x & 31;
    if (warp >= BL) return;
    float x[8];
    const float* row = data + (size_t)warp*H;
    #pragma unroll
    for (int t = 0; t < 8; t++) x[t] = row[t*32 + lane];
    for (int n = 0; n < NH; n++) {
        const float* A1 = a1 + n*3*H + H;
        const float* A2 = a2 + n*3*H + H;
        float s1 = 0.f, s2 = 0.f;
        #pragma unroll
        for (int t = 0; t < 8; t++) { int k = t*32+lane; s1 += x[t]*A1[2*k]; s2 += x[t]*A2[2*k]; }
        s1 = warp_sum(s1); s2 = warp_sum(s2);
        if (lane == 0) { g_d1[n*BL + warp] = s1; g_d2[n*BL + warp] = s2; }
    }
}

// ---------------- per-iteration kernels ----------------

// fused: (optional zeropad) + layernorm + ei/ej computation
__global__ void k_ln_eij(const float* __restrict__ gamma, const float* __restrict__ beta,
                         int apply_mask, const int* __restrict__ mask) {
    int warp = (blockIdx.x*blockDim.x + threadIdx.x) >> 5, lane = threadIdx.x & 31;
    if (warp >= BL) return;
    int b = warp >> 9;
    float x[8];
    float* nrow = g_nodes + (size_t)warp*H;
    bool zero = apply_mask && (mask[warp] == 0);
    float s = 0.f;
    #pragma unroll
    for (int t = 0; t < 8; t++) {
        x[t] = zero ? 0.f : nrow[t*32 + lane];
        s += x[t];
    }
    if (zero) {
        #pragma unroll
        for (int t = 0; t < 8; t++) nrow[t*32 + lane] = 0.f;
    }
    s = warp_sum(s);
    float mean = s * (1.0f/H);
    float v = 0.f;
    #pragma unroll
    for (int t = 0; t < 8; t++) { float d = x[t]-mean; v += d*d; }
    v = warp_sum(v);
    float rstd = rsqrtf(v * (1.0f/H) + 1e-5f);
    #pragma unroll
    for (int t = 0; t < 8; t++) {
        int h = t*32 + lane;
        x[t] = (x[t]-mean)*rstd*gamma[h] + beta[h];
        g_xn[(size_t)warp*H + h] = x[t];
    }
    // ei/ej per head using xn in registers
    for (int n = 0; n < NH; n++) {
        float s1 = 0.f, s2 = 0.f;
        #pragma unroll
        for (int t = 0; t < 8; t++) {
            int k = t*32+lane;
            s1 += x[t]*g_wa1[n*H + k];
            s2 += x[t]*g_wa2[n*H + k];
        }
        s1 = warp_sum(s1); s2 = warp_sum(s2);
        if (lane == 0) {
            g_ei[n*BL + warp] = s1 + g_d1[n*BL + warp] + g_r1[n*B + b] + g_c1[n];
            g_ej[n*BL + warp] = s2 + g_d2[n*BL + warp] + g_r2[n*B + b] + g_c2[n];
        }
    }
}

// relay-dependent small stuff: grid (B,2). y=0: grel + r1/r2; y=1: qproj (warp/output)
__global__ void k_relay_small(const float* __restrict__ a1, const float* __restrict__ a2,
                              const float* __restrict__ sqw, const float* __restrict__ sqb) {
    int b = blockIdx.x, t = threadIdx.x, lane = t & 31, w = t >> 5;
    __shared__ float sr[H];
    sr[t] = g_relay[b*H + t];
    __syncthreads();
    if (blockIdx.y == 0) {
        float s = 0.f;
        #pragma unroll 8
        for (int k = 0; k < H; k++) s += sr[k] * g_Hw[k*ND + t];
        g_grel[b*ND + t] = s;
        if (t < NH) {
            int n = t; float s1 = 0.f, s2 = 0.f;
            const float* A1 = a1 + n*3*H + H;
            const float* A2 = a2 + n*3*H + H;
            for (int k = 0; k < H; k++) { s1 += sr[k]*A1[2*k+1]; s2 += sr[k]*A2[2*k+1]; }
            g_r1[n*B + b] = s1; g_r2[n*B + b] = s2;
        }
    } else {
        for (int o = 0; o < 32; o++) {
            int c = w*32 + o;
            float acc = 0.f;
            #pragma unroll
            for (int q = 0; q < 8; q++)
                acc += sr[q*32 + lane] * sqw[(size_t)c*H + q*32 + lane];
            acc = warp_sum(acc);
            if (lane == 0) g_qproj[b*ND + c] = acc + sqb[c];
        }
    }
}

// ------- tf32 tensor-core GEMM: M tile 128, N tile 64, K=256, 8 warps -------
__global__ __launch_bounds__(256) void k_gemm_tf32(
        const float* __restrict__ A, const float* __restrict__ Bm,
        float* __restrict__ C, int bT, int ep,
        const float* __restrict__ bias,
        const float* __restrict__ add1, const float* __restrict__ add2) {
    __shared__ unsigned As[128][36];
    __shared__ unsigned Bs[32][72];
    int tid = threadIdx.x;
    int warp = tid >> 5, lane = tid & 31;
    int wm = warp >> 1, wn = warp & 1;
    int g = lane >> 2, tig = lane & 3;
    int tm = blockIdx.x * 128, tn = blockIdx.y * 64;

    float c[2][4][4];
    #pragma unroll
    for (int mt = 0; mt < 2; mt++)
        #pragma unroll
        for (int nt = 0; nt < 4; nt++)
            #pragma unroll
            for (int i = 0; i < 4; i++) c[mt][nt][i] = 0.f;

    for (int kb = 0; kb < 256; kb += 32) {
        #pragma unroll
        for (int j = 0; j < 4; j++) {
            int idx = tid + 256*j;
            int r = idx >> 3, c4 = (idx & 7) * 4;
            float4 v = *(const float4*)(A + (size_t)(tm + r)*256 + kb + c4);
            As[r][c4+0] = f2tf(v.x); As[r][c4+1] = f2tf(v.y);
            As[r][c4+2] = f2tf(v.z); As[r][c4+3] = f2tf(v.w);
        }
        if (!bT) {
            #pragma unroll
            for (int j = 0; j < 2; j++) {
                int idx = tid + 256*j;
                int r = idx >> 4, c4 = (idx & 15) * 4;
                float4 v = *(const float4*)(Bm + (size_t)(kb + r)*256 + tn + c4);
                Bs[r][c4+0] = f2tf(v.x); Bs[r][c4+1] = f2tf(v.y);
                Bs[r][c4+2] = f2tf(v.z); Bs[r][c4+3] = f2tf(v.w);
            }
        } else {
            #pragma unroll
            for (int j = 0; j < 2; j++) {
                int idx = tid + 256*j;
                int cc = idx & 63, q = idx >> 6;
                float4 v = *(const float4*)(Bm + (size_t)(tn + cc)*256 + kb + q*4);
                Bs[q*4+0][cc] = f2tf(v.x); Bs[q*4+1][cc] = f2tf(v.y);
                Bs[q*4+2][cc] = f2tf(v.z); Bs[q*4+3][cc] = f2tf(v.w);
            }
        }
        __syncthreads();
        #pragma unroll
        for (int ks = 0; ks < 32; ks += 8) {
            unsigned af[2][4], bf[4][2];
            #pragma unroll
            for (int mt = 0; mt < 2; mt++) {
                int R = wm*32 + mt*16;
                af[mt][0] = As[R+g  ][ks+tig  ];
                af[mt][1] = As[R+g+8][ks+tig  ];
                af[mt][2] = As[R+g  ][ks+tig+4];
                af[mt][3] = As[R+g+8][ks+tig+4];
            }
            #pragma unroll
            for (int nt = 0; nt < 4; nt++) {
                int Cn = wn*32 + nt*8;
                bf[nt][0] = Bs[ks+tig  ][Cn+g];
                bf[nt][1] = Bs[ks+tig+4][Cn+g];
            }
            #pragma unroll
            for (int mt = 0; mt < 2; mt++)
                #pragma unroll
                for (int nt = 0; nt < 4; nt++)
                    mma8(c[mt][nt], af[mt], bf[nt]);
        }
        __syncthreads();
    }
    #pragma unroll
    for (int mt = 0; mt < 2; mt++) {
        #pragma unroll
        for (int nt = 0; nt < 4; nt++) {
            #pragma unroll
            for (int half = 0; half < 2; half++) {
                int r = tm + wm*32 + mt*16 + g + half*8;
                int col = tn + wn*32 + nt*8 + tig*2;
                float v0 = c[mt][nt][half*2+0];
                float v1 = c[mt][nt][half*2+1];
                if (bias) { v0 += bias[col]; v1 += bias[col+1]; }
                if (ep == 1) {
                    v0 += add1[(size_t)r*256 + col]   + add2[(r>>9)*256 + col];
                    v1 += add1[(size_t)r*256 + col+1] + add2[(r>>9)*256 + col+1];
                    float2 o = {v0, v1};
                    *(float2*)(C + (size_t)r*256 + col) = o;
                } else if (ep == 2) {
                    v0 = v0 > 0.f ? v0 : 0.01f*v0;
                    v1 = v1 > 0.f ? v1 : 0.01f*v1;
                    float2 old = *(float2*)(C + (size_t)r*256 + col);
                    float2 o = {old.x + v0, old.y + v1};
                    *(float2*)(C + (size_t)r*256 + col) = o;
                } else if (ep == 3) {
                    int orow = (r>>9)*LP1 + (r & 511) + 1;
                    float2 o = {v0, v1};
                    *(float2*)(C + (size_t)orow*256 + col) = o;
                } else {
                    float2 o = {v0, v1};
                    *(float2*)(C + (size_t)r*256 + col) = o;
                }
            }
        }
    }
}

// ------- GAT attention via factorized-exp weights + tensor-core weighted sum -------
// grid (NH*B, 2), 256 threads. i-tile = 256 rows, j-chunk = 64.
// B-operand sgt[j][44]: cols 0..31 = g, col 32 = 1 (gives denominator), 33..39 = 0.
__global__ __launch_bounds__(256) void k_gat_attn2(const float* __restrict__ fcb) {
    extern __shared__ char smraw[];
    unsigned* sgt  = (unsigned*)smraw;               // 512*44
    unsigned* ws   = sgt + 512*44;                   // 256*68
    float*    sej  = (float*)(ws + 256*68);          // 512
    float*    sE   = sej + 512;                      // 512
    float*    sF   = sE + 512;                       // 512
    float4*   sRow = (float4*)(sF + 512);            // 256 (A, C, eii, degflag)
    unsigned* sadj = (unsigned*)(sRow + 256);        // 256*16
    float*    sred = (float*)(sadj + 256*16);        // 8

    int n = blockIdx.x & 7, b = blockIdx.x >> 3;
    int i0 = blockIdx.y * 256;
    int tid = threadIdx.x, lane = tid & 31, wrp = tid >> 5;
    int g = lane >> 2, tig = lane & 3;

    // stage ej
    for (int l = tid; l < L; l += 256) sej[l] = g_ej[n*BL + b*L + l];
    // stage g (transposed to [j][col], tf32) + ones column
    for (int j = tid; j < L; j += 256) {
        const float4* gr = (const float4*)(g_gbuf + ((size_t)(b*L + j))*ND + n*HD);
        unsigned* dst = sgt + j*44;
        #pragma unroll
        for (int q = 0; q < 8; q++) {
            float4 v = gr[q];
            dst[q*4+0]=f2tf(v.x); dst[q*4+1]=f2tf(v.y);
            dst[q*4+2]=f2tf(v.z); dst[q*4+3]=f2tf(v.w);
        }
        dst[32] = f2tf(1.0f);
        #pragma unroll
        for (int q = 33; q < 40; q++) dst[q] = 0u;
    }
    // stage adjacency for this i-tile
    for (int idx = tid; idx < 256*16; idx += 256)
        sadj[idx] = g_adj[((size_t)(b*L) + i0 + (idx>>4))*LW + (idx & 15)];
    __syncthreads();

    // global max of ej for this (b,n)
    float mx = -1e30f;
    for (int l = tid; l < L; l += 256) mx = fmaxf(mx, sej[l]);
    mx = warp_max(mx);
    if (lane == 0) sred[wrp] = mx;
    __syncthreads();
    float mj = fmaxf(fmaxf(fmaxf(sred[0],sred[1]),fmaxf(sred[2],sred[3])),
                     fmaxf(fmaxf(sred[4],sred[5]),fmaxf(sred[6],sred[7])));
    // E = exp(ej - mj), F = exp(0.2(ej - mj))
    for (int l = tid; l < L; l += 256) {
        float d = sej[l] - mj;
        sE[l] = __expf(d);
        sF[l] = __expf(0.2f*d);
    }
    // per-row constants (warp wrp owns rows wrp*32..+31)
    for (int rr = 0; rr < 32; rr++) {
        int r = wrp*32 + rr;
        float mxa = -1e30f;
        #pragma unroll
        for (int t = 0; t < LW; t++)
            if ((sadj[r*16 + t] >> lane) & 1u) mxa = fmaxf(mxa, sej[t*32 + lane]);
        mxa = warp_max(mxa);
        if (lane == 0) {
            float4 rc;
            if (mxa < -5e29f) {
                rc = make_float4(0.f, 0.f, 0.f, 1.f);   // degenerate: uniform weights
            } else {
                float eii = g_ei[n*BL + b*L + i0 + r];
                float M = eii + mxa; M = M > 0.f ? M : 0.2f*M;
                // clamp exponents: mathematically a no-op when weights are
                // representable (adjacent-j products are always <= 1)
                rc.x = __expf(fminf(eii + mj - M, 80.f));          // A
                rc.y = __expf(fminf(0.2f*(eii + mj) - M, 80.f));   // C
                rc.z = eii;
                rc.w = 0.f;
            }
            sRow[r] = rc;
        }
    }
    __syncthreads();

    float c[2][5][4];
    #pragma unroll
    for (int mt = 0; mt < 2; mt++)
        #pragma unroll
        for (int nt = 0; nt < 5; nt++)
            #pragma unroll
            for (int i = 0; i < 4; i++) c[mt][nt][i] = 0.f;

    for (int jc = 0; jc < 8; jc++) {
        int jbase = jc*64;
        float ejv0 = sej[jbase + lane],    ejv1 = sej[jbase + 32 + lane];
        float E0   = sE[jbase + lane],     E1   = sE[jbase + 32 + lane];
        float F0   = sF[jbase + lane],     F1   = sF[jbase + 32 + lane];
        // generate weights for rows wrp*32..+31, j in [jbase, jbase+64)
        for (int rr = 0; rr < 32; rr++) {
            int r = wrp*32 + rr;
            float4 rc = sRow[r];
            unsigned w0 = sadj[r*16 + jc*2], w1 = sadj[r*16 + jc*2 + 1];
            float v0, v1;
            if (rc.w != 0.f) {
                v0 = 1.0f/512.0f; v1 = 1.0f/512.0f;
            } else {
                v0 = ((w0>>lane)&1u) ? ((rc.z + ejv0 > 0.f) ? rc.x*E0 : rc.y*F0) : 0.f;
                v1 = ((w1>>lane)&1u) ? ((rc.z + ejv1 > 0.f) ? rc.x*E1 : rc.y*F1) : 0.f;
            }
            ws[r*68 + lane]      = f2tf(v0);
            ws[r*68 + 32 + lane] = f2tf(v1);
        }
        __syncthreads();
        // mma: [32 rows x 64 j] @ [64 j x 40 cols]
        #pragma unroll
        for (int ks = 0; ks < 64; ks += 8) {
            unsigned af[2][4];
            #pragma unroll
            for (int mt = 0; mt < 2; mt++) {
                int R = wrp*32 + mt*16;
                af[mt][0] = ws[(R+g  )*68 + ks + tig    ];
                af[mt][1] = ws[(R+g+8)*68 + ks + tig    ];
                af[mt][2] = ws[(R+g  )*68 + ks + tig + 4];
                af[mt][3] = ws[(R+g+8)*68 + ks + tig + 4];
            }
            #pragma unroll
            for (int nt = 0; nt < 5; nt++) {
                unsigned bf[2];
                bf[0] = sgt[(jbase+ks+tig  )*44 + nt*8 + g];
                bf[1] = sgt[(jbase+ks+tig+4)*44 + nt*8 + g];
                mma8(c[0][nt], af[0], bf);
                mma8(c[1][nt], af[1], bf);
            }
        }
        __syncthreads();
    }

    // epilogue: divide by denominator (col 32), + bias, elu, store
    #pragma unroll
    for (int mt = 0; mt < 2; mt++) {
        float den0 = __shfl_sync(0xffffffffu, c[mt][4][0], lane & ~3);
        float den8 = __shfl_sync(0xffffffffu, c[mt][4][2], lane & ~3);
        float inv0 = 1.0f / den0, inv8 = 1.0f / den8;
        int r0 = i0 + wrp*32 + mt*16 + g;
        #pragma unroll
        for (int nt = 0; nt < 4; nt++) {
            int col = nt*8 + tig*2;
            float b0 = fcb[n*HD + col], b1 = fcb[n*HD + col + 1];
            float o00 = c[mt][nt][0]*inv0 + b0, o01 = c[mt][nt][1]*inv0 + b1;
            float o10 = c[mt][nt][2]*inv8 + b0, o11 = c[mt][nt][3]*inv8 + b1;
            o00 = o00 > 0.f ? o00 : expm1f(o00);
            o01 = o01 > 0.f ? o01 : expm1f(o01);
            o10 = o10 > 0.f ? o10 : expm1f(o10);
            o11 = o11 > 0.f ? o11 : expm1f(o11);
            float2 a = {o00, o01}, bb = {o10, o11};
            *(float2*)(g_temp + ((size_t)(b*L) + r0    )*ND + n*HD + col) = a;
            *(float2*)(g_temp + ((size_t)(b*L) + r0 + 8)*ND + n*HD + col) = bb;
        }
    }
}

// star-attn row 0 of kproj: relay @ sk_w^T + sk_b  (warp-per-output)
__global__ void k_kproj0(const float* __restrict__ skw, const float* __restrict__ skb) {
    int b = blockIdx.x, t = threadIdx.x, lane = t & 31, w = t >> 5;
    __shared__ float sr[H];
    sr[t] = g_relay[b*H + t];
    __syncthreads();
    for (int o = 0; o < 32; o++) {
        int c = w*32 + o;
        float acc = 0.f;
        #pragma unroll
        for (int q = 0; q < 8; q++)
            acc += sr[q*32 + lane] * skw[(size_t)c*H + q*32 + lane];
        acc = warp_sum(acc);
        if (lane == 0) g_kproj[(size_t)b*LP1*ND + c] = acc + skb[c];
    }
}

// fused star attention: grid (B, NH), 256 threads
__global__ void k_star(const int* __restrict__ mask) {
    __shared__ float sq[HD];
    __shared__ float sw[LP1];
    __shared__ float redm[8];
    __shared__ float reds[8];
    __shared__ float part[8][HD];
    int b = blockIdx.x, n = blockIdx.y;
    int tid = threadIdx.x, lane = tid & 31, w = tid >> 5;
    if (tid < HD) sq[tid] = g_qproj[b*ND + n*HD + tid];
    __syncthreads();
    const float scale = 0.17677669529663689f;
    const float* kp = g_kproj + (size_t)b*LP1*ND + n*HD;
    for (int l = tid; l < LP1; l += 256) {
        bool valid = (l == 0) || (mask[b*L + l - 1] != 0);
        float s = -1e30f;
        if (valid) {
            const float4* row = (const float4*)(kp + (size_t)l*ND);
            float acc = 0.f;
            #pragma unroll
            for (int q = 0; q < 8; q++) {
                float4 v = row[q];
                acc += v.x*sq[q*4+0] + v.y*sq[q*4+1] + v.z*sq[q*4+2] + v.w*sq[q*4+3];
            }
            s = acc * scale;
        }
        sw[l] = s;
    }
    __syncthreads();
    float mx = -1e30f;
    for (int l = tid; l < LP1; l += 256) mx = fmaxf(mx, sw[l]);
    mx = warp_max(mx);
    if (lane == 0) redm[w] = mx;
    __syncthreads();
    if (w == 0) {
        float v = (lane < 8) ? redm[lane] : -1e30f;
        v = warp_max(v);
        if (lane == 0) redm[0] = v;
    }
    __syncthreads();
    mx = redm[0];
    float sum = 0.f;
    for (int l = tid; l < LP1; l += 256) {
        float e = __expf(sw[l] - mx);
        sw[l] = e;
        sum += e;
    }
    sum = warp_sum(sum);
    if (lane == 0) reds[w] = sum;
    __syncthreads();
    float total = 0.f;
    #pragma unroll
    for (int u = 0; u < 8; u++) total += reds[u];
    float inv = 1.0f / total;
    float acc = 0.f;
    for (int l = w; l < LP1; l += 8)
        acc += sw[l] * kp[(size_t)l*ND + lane];
    part[w][lane] = acc;
    __syncthreads();
    if (w == 0) {
        float a = 0.f;
        #pragma unroll
        for (int u = 0; u < 8; u++) a += part[u][lane];
        g_attv[b*ND + n*HD + lane] = a * inv;
    }
}

// relay = lrelu(attv @ so_w^T + so_b, 0.01)  (warp-per-output)
__global__ void k_so(const float* __restrict__ sow, const float* __restrict__ sob) {
    int b = blockIdx.x, t = threadIdx.x, lane = t & 31, w = t >> 5;
    __shared__ float sa[ND];
    sa[t] = g_attv[b*ND + t];
    __syncthreads();
    for (int o = 0; o < 32; o++) {
        int h = w*32 + o;
        float acc = 0.f;
        #pragma unroll
        for (int q = 0; q < 8; q++)
            acc += sa[q*32 + lane] * sow[(size_t)h*ND + q*32 + lane];
        acc = warp_sum(acc);
        if (lane == 0) {
            float s = acc + sob[h];
            g_relay[b*H + h] = s > 0.f ? s : 0.01f*s;
        }
    }
}

__global__ void k_out(float* __restrict__ out, int total, const int* __restrict__ mask) {
    int idx = blockIdx.x*blockDim.x + threadIdx.x;
    if (idx >= total) return;
    if (idx < BL*H) out[idx] = (mask[idx >> 8] != 0) ? g_nodes[idx] : 0.f;
    else            out[idx] = g_relay[idx - BL*H];
}

// ---------------- launch ----------------
extern "C" void kernel_launch(void* const* d_in, const int* in_sizes, int n_in,
                              void* d_out, int out_size) {
    const float* data    = (const float*)d_in[0];
    const float* WQw     = (const float*)d_in[1];
    const float* WQb     = (const float*)d_in[2];
    const float* a1      = (const float*)d_in[3];
    const float* a2      = (const float*)d_in[4];
    const float* fcw_gat = (const float*)d_in[5];
    const float* fcb_gat = (const float*)d_in[6];
    const float* norm_g  = (const float*)d_in[7];
    const float* norm_b  = (const float*)d_in[8];
    const float* sq_w    = (const float*)d_in[9];
    const float* sq_b    = (const float*)d_in[10];
    const float* sk_w    = (const float*)d_in[11];
    const float* sk_b    = (const float*)d_in[12];
    const float* so_w    = (const float*)d_in[13];
    const float* so_b    = (const float*)d_in[14];
    const float* fc_w    = (const float*)d_in[15];
    const float* fc_b    = (const float*)d_in[16];
    const int*   mask    = (const int*)d_in[17];
    const int*   edge    = (const int*)d_in[18];
    float* out = (float*)d_out;

    const int GAT_SMEM = (512*44 + 256*68 + 512*3 + 256*4 + 256*16 + 16) * (int)sizeof(float);
    cudaFuncSetAttribute(k_gat_attn2, cudaFuncAttributeMaxDynamicSharedMemorySize, GAT_SMEM);

    float *p_nodes, *p_xn, *p_gdat, *p_gbuf, *p_temp, *p_Mcat, *p_Gw, *p_bqF, *p_grel, *p_kproj;
    cudaGetSymbolAddress((void**)&p_nodes, g_nodes);
    cudaGetSymbolAddress((void**)&p_xn,    g_xn);
    cudaGetSymbolAddress((void**)&p_gdat,  g_gdat);
    cudaGetSymbolAddress((void**)&p_gbuf,  g_gbuf);
    cudaGetSymbolAddress((void**)&p_temp,  g_temp);
    cudaGetSymbolAddress((void**)&p_Mcat,  g_Mcat);
    cudaGetSymbolAddress((void**)&p_Gw,    g_Gw);
    cudaGetSymbolAddress((void**)&p_bqF,   g_bqF);
    cudaGetSymbolAddress((void**)&p_grel,  g_grel);
    cudaGetSymbolAddress((void**)&p_kproj, g_kproj);

    cudaMemcpyAsync(p_nodes, data, sizeof(float)*BL*H, cudaMemcpyDeviceToDevice);
    cudaMemsetAsync(p_Mcat, 0, sizeof(float)*H*ND);

    k_pack_adj<<<1024, 256>>>(edge);
    k_relay0<<<B, 256>>>(data);
    k_prep_wa<<<NH, 256>>>(WQw, WQb, a1, a2);
    k_prep_bqF<<<NH, 256>>>(WQb, fcw_gat);
    k_prep_GH<<<(H*ND + 255)/256, 256>>>(fcw_gat);
    k_prep_Mcat<<<dim3(NH, 2), 256>>>(WQw, fcw_gat);
    k_d12<<<1024, 256>>>(data, a1, a2);
    k_gemm_tf32<<<dim3(64, 4), 256>>>(data, p_Gw, p_gdat, 0, 0, nullptr, nullptr, nullptr);

    for (int i = 0; i < ITR; i++) {
        k_relay_small<<<dim3(B, 2), 256>>>(a1, a2, sq_w + (size_t)i*ND*H, sq_b + i*ND);
        k_ln_eij<<<1024, 256>>>(norm_g + i*H, norm_b + i*H, i > 0 ? 1 : 0, mask);
        // g = xn @ Mcat + bqF + gdat + grel
        k_gemm_tf32<<<dim3(64, 4), 256>>>(p_xn, p_Mcat, p_gbuf, 0, 1, p_bqF, p_gdat, p_grel);
        k_gat_attn2<<<dim3(NH*B, 2), 256, GAT_SMEM>>>(fcb_gat);
        // nodes += lrelu(temp @ fc_w + fc_b)
        k_gemm_tf32<<<dim3(64, 4), 256>>>(p_temp, fc_w, p_nodes, 0, 2, fc_b, nullptr, nullptr);
        // star attention
        k_kproj0<<<B, 256>>>(sk_w + (size_t)i*ND*H, sk_b + i*ND);
        k_gemm_tf32<<<dim3(64, 4), 256>>>(p_nodes, sk_w + (size_t)i*ND*H, p_kproj, 1, 3,
                                          sk_b + i*ND, nullptr, nullptr);
        k_star<<<dim3(B, NH), 256>>>(mask);
        k_so<<<B, 256>>>(so_w + (size_t)i*H*ND, so_b + i*H);
    }

    int total = BL*H + B*H;
    if (total > out_size) total = out_size;
    k_out<<<(total + 255)/256, 256>>>(out, total, mask);
}

// round 10
// speedup vs baseline: 2.5060x; 1.0440x over previous
#include <cuda_runtime.h>
#include <math.h>

#define B   16
#define L   512
#define H   256
#define NH  8
#define HD  32
#define ND  256        // NH*HD
#define ITR 2
#define BL  (B*L)      // 8192
#define LP1 (L+1)      // 513
#define LW  (L/32)     // 16 adjacency words per row

// ---------------- device scratch (no allocs allowed) ----------------
__device__ float    g_nodes[BL*H];
__device__ float    g_xn[BL*H];
__device__ float    g_relay[B*H];
__device__ float    g_d1[NH*BL];
__device__ float    g_d2[NH*BL];
__device__ float    g_ei[NH*BL];
__device__ float    g_ej[NH*BL];
__device__ float    g_gdat[BL*ND];
__device__ float    g_gbuf[BL*ND];
__device__ float    g_temp[BL*ND];
__device__ float    g_wa1[NH*H];
__device__ float    g_wa2[NH*H];
__device__ float    g_c1[NH];
__device__ float    g_c2[NH];
__device__ float    g_bqF[ND];
__device__ float    g_Mcat[H*ND];
__device__ float    g_Gw[H*ND];
__device__ float    g_Hw[H*ND];
__device__ unsigned g_adj[BL*LW];
__device__ float    g_r1[NH*B];
__device__ float    g_r2[NH*B];
__device__ float    g_grel[B*ND];
__device__ float    g_kproj[B*LP1*ND];
__device__ float    g_qproj[B*ND];
__device__ float    g_attv[B*ND];

__device__ __forceinline__ float warp_sum(float v) {
    #pragma unroll
    for (int o = 16; o; o >>= 1) v += __shfl_xor_sync(0xffffffffu, v, o);
    return v;
}
__device__ __forceinline__ float warp_max(float v) {
    #pragma unroll
    for (int o = 16; o; o >>= 1) v = fmaxf(v, __shfl_xor_sync(0xffffffffu, v, o));
    return v;
}
__device__ __forceinline__ unsigned f2tf(float f) {
    unsigned u; asm("cvt.rna.tf32.f32 %0, %1;" : "=r"(u) : "f"(f)); return u;
}
__device__ __forceinline__ void mma8(float* c, const unsigned* a, const unsigned* b) {
    asm volatile("mma.sync.aligned.m16n8k8.row.col.f32.tf32.tf32.f32 "
        "{%0,%1,%2,%3}, {%4,%5,%6,%7}, {%8,%9}, {%0,%1,%2,%3};"
        : "+f"(c[0]), "+f"(c[1]), "+f"(c[2]), "+f"(c[3])
        : "r"(a[0]), "r"(a[1]), "r"(a[2]), "r"(a[3]), "r"(b[0]), "r"(b[1]));
}

// ---------------- one-time-per-launch prep ----------------

__global__ void k_pack_adj(const int* __restrict__ edge) {
    int warp = (blockIdx.x * blockDim.x + threadIdx.x) >> 5;
    int lane = threadIdx.x & 31;
    if (warp >= BL) return;
    const int* row = edge + (size_t)warp * L;
    #pragma unroll
    for (int t = 0; t < LW; t++) {
        unsigned m = __ballot_sync(0xffffffffu, row[t*32 + lane] > 0);
        if (lane == 0) g_adj[warp*LW + t] = m;
    }
}

// merged prologue smalls: blocks [0,16)=relay0, [16,24)=prep_wa,
// [24,32)=prep_bqF, [32,288)=prep_GH
__global__ void k_prep_small(const float* __restrict__ data,
                             const float* __restrict__ Wq, const float* __restrict__ bq,
                             const float* __restrict__ a1, const float* __restrict__ a2,
                             const float* __restrict__ fcw) {
    int blk = blockIdx.x, tid = threadIdx.x;
    if (blk < 16) {                       // relay0
        int b = blk, h = tid;
        float s = 0.f;
        #pragma unroll 8
        for (int l = 0; l < L; l++) s += data[((size_t)b*L + l)*H + h];
        g_relay[b*H + h] = s * (1.0f/L);
    } else if (blk < 24) {                // prep_wa
        int n = blk - 16, m = tid;
        const float* W  = Wq + (size_t)n*H*H;
        const float* A1 = a1 + n*3*H;
        const float* A2 = a2 + n*3*H;
        float s1 = 0.f, s2 = 0.f;
        #pragma unroll 8
        for (int k = 0; k < H; k++) { float w = W[k*H + m]; s1 += A1[k]*w; s2 += A2[k]*w; }
        g_wa1[n*H + m] = s1; g_wa2[n*H + m] = s2;
        if (m == 0) {
            float c1 = 0.f, c2 = 0.f;
            for (int k = 0; k < H; k++) { c1 += A1[k]*bq[n*H + k]; c2 += A2[k]*bq[n*H + k]; }
            g_c1[n] = c1; g_c2[n] = c2;
        }
    } else if (blk < 32) {                // prep_bqF
        __shared__ float red[8][HD];
        int n = blk - 24, d = tid & 31, kw = tid >> 5;
        float s = 0.f;
        #pragma unroll
        for (int q = 0; q < 32; q++) {
            int k = kw*32 + q;
            s += bq[n*H + k] * fcw[((size_t)n*3*H + k)*HD + d];
        }
        red[kw][d] = s;
        __syncthreads();
        if (kw == 0) {
            float a = 0.f;
            #pragma unroll
            for (int u = 0; u < 8; u++) a += red[u][d];
            g_bqF[n*HD + d] = a;
        }
    } else {                              // prep_GH
        int idx = (blk - 32)*256 + tid;
        int k = idx >> 8, c = idx & 255, n = c >> 5, d = c & 31;
        g_Gw[idx] = fcw[((size_t)n*3*H + (H + 2*k    ))*HD + d];
        g_Hw[idx] = fcw[((size_t)n*3*H + (H + 2*k + 1))*HD + d];
    }
}

__global__ void k_prep_Mcat(const float* __restrict__ Wq, const float* __restrict__ fcw) {
    __shared__ float sF[128*HD];
    int n = blockIdx.x, half = blockIdx.y, m = threadIdx.x;
    int k0 = half * 128;
    for (int i = m; i < 128*HD; i += blockDim.x)
        sF[i] = fcw[(size_t)n*3*H*HD + (size_t)k0*HD + i];
    __syncthreads();
    float acc[HD];
    #pragma unroll
    for (int d = 0; d < HD; d++) acc[d] = 0.f;
    const float* W = Wq + (size_t)n*H*H + (size_t)k0*H;
    for (int k = 0; k < 128; k++) {
        float w = W[k*H + m];
        #pragma unroll
        for (int d = 0; d < HD; d++) acc[d] += w * sF[k*HD + d];
    }
    #pragma unroll
    for (int d = 0; d < HD; d++) atomicAdd(&g_Mcat[m*ND + n*HD + d], acc[d]);
}

__global__ void k_d12(const float* __restrict__ data, const float* __restrict__ a1,
                      const float* __restrict__ a2) {
    int warp = (blockIdx.x*blockDim.x + threadIdx.x) >> 5, lane = threadIdx.x & 31;
    if (warp >= BL) return;
    float x[8];
    const float* row = data + (size_t)warp*H;
    #pragma unroll
    for (int t = 0; t < 8; t++) x[t] = row[t*32 + lane];
    for (int n = 0; n < NH; n++) {
        const float* A1 = a1 + n*3*H + H;
        const float* A2 = a2 + n*3*H + H;
        float s1 = 0.f, s2 = 0.f;
        #pragma unroll
        for (int t = 0; t < 8; t++) { int k = t*32+lane; s1 += x[t]*A1[2*k]; s2 += x[t]*A2[2*k]; }
        s1 = warp_sum(s1); s2 = warp_sum(s2);
        if (lane == 0) { g_d1[n*BL + warp] = s1; g_d2[n*BL + warp] = s2; }
    }
}

// relay-dependent small stuff for iter 0: grid (B,2)
__global__ void k_relay_small(const float* __restrict__ a1, const float* __restrict__ a2,
                              const float* __restrict__ sqw, const float* __restrict__ sqb) {
    int b = blockIdx.x, t = threadIdx.x, lane = t & 31, w = t >> 5;
    __shared__ float sr[H];
    sr[t] = g_relay[b*H + t];
    __syncthreads();
    if (blockIdx.y == 0) {
        float s = 0.f;
        #pragma unroll 8
        for (int k = 0; k < H; k++) s += sr[k] * g_Hw[k*ND + t];
        g_grel[b*ND + t] = s;
        if (t < NH) {
            int n = t; float s1 = 0.f, s2 = 0.f;
            const float* A1 = a1 + n*3*H + H;
            const float* A2 = a2 + n*3*H + H;
            for (int k = 0; k < H; k++) { s1 += sr[k]*A1[2*k+1]; s2 += sr[k]*A2[2*k+1]; }
            g_r1[n*B + b] = s1; g_r2[n*B + b] = s2;
        }
    } else {
        for (int o = 0; o < 32; o++) {
            int c = w*32 + o;
            float acc = 0.f;
            #pragma unroll
            for (int q = 0; q < 8; q++)
                acc += sr[q*32 + lane] * sqw[(size_t)c*H + q*32 + lane];
            acc = warp_sum(acc);
            if (lane == 0) g_qproj[b*ND + c] = acc + sqb[c];
        }
    }
}

// ---------------- per-iteration kernels ----------------

// fused: (optional zeropad) + layernorm + ei/ej
__global__ void k_ln_eij(const float* __restrict__ gamma, const float* __restrict__ beta,
                         int apply_mask, const int* __restrict__ mask) {
    int warp = (blockIdx.x*blockDim.x + threadIdx.x) >> 5, lane = threadIdx.x & 31;
    if (warp >= BL) return;
    int b = warp >> 9;
    float x[8];
    float* nrow = g_nodes + (size_t)warp*H;
    bool zero = apply_mask && (mask[warp] == 0);
    float s = 0.f;
    #pragma unroll
    for (int t = 0; t < 8; t++) {
        x[t] = zero ? 0.f : nrow[t*32 + lane];
        s += x[t];
    }
    if (zero) {
        #pragma unroll
        for (int t = 0; t < 8; t++) nrow[t*32 + lane] = 0.f;
    }
    s = warp_sum(s);
    float mean = s * (1.0f/H);
    float v = 0.f;
    #pragma unroll
    for (int t = 0; t < 8; t++) { float d = x[t]-mean; v += d*d; }
    v = warp_sum(v);
    float rstd = rsqrtf(v * (1.0f/H) + 1e-5f);
    #pragma unroll
    for (int t = 0; t < 8; t++) {
        int h = t*32 + lane;
        x[t] = (x[t]-mean)*rstd*gamma[h] + beta[h];
        g_xn[(size_t)warp*H + h] = x[t];
    }
    for (int n = 0; n < NH; n++) {
        float s1 = 0.f, s2 = 0.f;
        #pragma unroll
        for (int t = 0; t < 8; t++) {
            int k = t*32+lane;
            s1 += x[t]*g_wa1[n*H + k];
            s2 += x[t]*g_wa2[n*H + k];
        }
        s1 = warp_sum(s1); s2 = warp_sum(s2);
        if (lane == 0) {
            g_ei[n*BL + warp] = s1 + g_d1[n*BL + warp] + g_r1[n*B + b] + g_c1[n];
            g_ej[n*BL + warp] = s2 + g_d2[n*BL + warp] + g_r2[n*B + b] + g_c2[n];
        }
    }
}

// ------- tf32 GEMM, software-pipelined + double-buffered smem -------
// M tile 128, N tile 64, K=256, chunk 32, 8 warps. Dynamic smem 55296 B.
// ep: 0 plain(+bias)  1 +bias+add1[r]+add2[b]  2 C += lrelu(acc+bias)
//     3 kproj row remap (b*513+l+1); blockIdx.x==64 computes kproj row 0
#define ASZ (128*36)
#define BSZ (32*72)
__device__ __forceinline__ void gemm_loadA(const float* A, int tm, int kb, int tid, float4* ra) {
    #pragma unroll
    for (int j = 0; j < 4; j++) {
        int idx = tid + 256*j;
        int r = idx >> 3, c4 = (idx & 7) * 4;
        ra[j] = *(const float4*)(A + (size_t)(tm + r)*256 + kb + c4);
    }
}
__device__ __forceinline__ void gemm_loadB(const float* Bm, int tn, int kb, int tid, int bT, float4* rb) {
    #pragma unroll
    for (int j = 0; j < 2; j++) {
        int idx = tid + 256*j;
        if (!bT) {
            int r = idx >> 4, c4 = (idx & 15) * 4;
            rb[j] = *(const float4*)(Bm + (size_t)(kb + r)*256 + tn + c4);
        } else {
            int cc = idx & 63, q = idx >> 6;
            rb[j] = *(const float4*)(Bm + (size_t)(tn + cc)*256 + kb + q*4);
        }
    }
}
__device__ __forceinline__ void gemm_store(unsigned* dynsm, int buf, int tid, int bT,
                                           const float4* ra, const float4* rb) {
    #pragma unroll
    for (int j = 0; j < 4; j++) {
        int idx = tid + 256*j;
        int r = idx >> 3, c4 = (idx & 7) * 4;
        unsigned* d = dynsm + buf*ASZ + r*36 + c4;
        d[0]=f2tf(ra[j].x); d[1]=f2tf(ra[j].y); d[2]=f2tf(ra[j].z); d[3]=f2tf(ra[j].w);
    }
    unsigned* bbase = dynsm + 2*ASZ;
    #pragma unroll
    for (int j = 0; j < 2; j++) {
        int idx = tid + 256*j;
        if (!bT) {
            int r = idx >> 4, c4 = (idx & 15) * 4;
            unsigned* d = bbase + buf*BSZ + r*72 + c4;
            d[0]=f2tf(rb[j].x); d[1]=f2tf(rb[j].y); d[2]=f2tf(rb[j].z); d[3]=f2tf(rb[j].w);
        } else {
            int cc = idx & 63, q = idx >> 6;
            unsigned* d = bbase + buf*BSZ + cc;
            d[(q*4+0)*72]=f2tf(rb[j].x); d[(q*4+1)*72]=f2tf(rb[j].y);
            d[(q*4+2)*72]=f2tf(rb[j].z); d[(q*4+3)*72]=f2tf(rb[j].w);
        }
    }
}

__global__ __launch_bounds__(256) void k_gemm_tf32(
        const float* __restrict__ A, const float* __restrict__ Bm,
        float* __restrict__ C, int bT, int ep,
        const float* __restrict__ bias,
        const float* __restrict__ add1, const float* __restrict__ add2) {
    extern __shared__ unsigned dynsm[];
    int tid = threadIdx.x;
    int warp = tid >> 5, lane = tid & 31;

    if (ep == 3 && blockIdx.x == 64) {
        // fused kproj row-0: relay @ sk_w^T + sk_b, column slice per blockIdx.y
        float* sr = (float*)dynsm;                     // [B*H]
        for (int i = tid; i < B*H; i += 256) sr[i] = g_relay[i];
        __syncthreads();
        int y = blockIdx.y;
        for (int bb = 0; bb < B; bb++) {
            #pragma unroll
            for (int o = 0; o < 8; o++) {
                int cidx = y*64 + warp*8 + o;
                float acc = 0.f;
                #pragma unroll
                for (int q = 0; q < 8; q++)
                    acc += sr[bb*H + q*32 + lane] * Bm[(size_t)cidx*H + q*32 + lane];
                acc = warp_sum(acc);
                if (lane == 0) C[(size_t)bb*LP1*ND + cidx] = acc + bias[cidx];
            }
        }
        return;
    }

    int wm = warp >> 1, wn = warp & 1;
    int g = lane >> 2, tig = lane & 3;
    int tm = blockIdx.x * 128, tn = blockIdx.y * 64;

    float c[2][4][4];
    #pragma unroll
    for (int mt = 0; mt < 2; mt++)
        #pragma unroll
        for (int nt = 0; nt < 4; nt++)
            #pragma unroll
            for (int i = 0; i < 4; i++) c[mt][nt][i] = 0.f;

    float4 ra[4], rb[2];
    gemm_loadA(A, tm, 0, tid, ra);
    gemm_loadB(Bm, tn, 0, tid, bT, rb);
    gemm_store(dynsm, 0, tid, bT, ra, rb);
    __syncthreads();

    for (int ch = 0; ch < 8; ch++) {
        int buf = ch & 1;
        if (ch + 1 < 8) {
            gemm_loadA(A, tm, (ch+1)*32, tid, ra);
            gemm_loadB(Bm, tn, (ch+1)*32, tid, bT, rb);
        }
        const unsigned* As = dynsm + buf*ASZ;
        const unsigned* Bs = dynsm + 2*ASZ + buf*BSZ;
        #pragma unroll
        for (int ks = 0; ks < 32; ks += 8) {
            unsigned af[2][4], bf[4][2];
            #pragma unroll
            for (int mt = 0; mt < 2; mt++) {
                int R = wm*32 + mt*16;
                af[mt][0] = As[(R+g  )*36 + ks+tig  ];
                af[mt][1] = As[(R+g+8)*36 + ks+tig  ];
                af[mt][2] = As[(R+g  )*36 + ks+tig+4];
                af[mt][3] = As[(R+g+8)*36 + ks+tig+4];
            }
            #pragma unroll
            for (int nt = 0; nt < 4; nt++) {
                int Cn = wn*32 + nt*8;
                bf[nt][0] = Bs[(ks+tig  )*72 + Cn+g];
                bf[nt][1] = Bs[(ks+tig+4)*72 + Cn+g];
            }
            #pragma unroll
            for (int mt = 0; mt < 2; mt++)
                #pragma unroll
                for (int nt = 0; nt < 4; nt++)
                    mma8(c[mt][nt], af[mt], bf[nt]);
        }
        if (ch + 1 < 8) {
            gemm_store(dynsm, (ch+1) & 1, tid, bT, ra, rb);
            __syncthreads();
        }
    }

    #pragma unroll
    for (int mt = 0; mt < 2; mt++) {
        #pragma unroll
        for (int nt = 0; nt < 4; nt++) {
            #pragma unroll
            for (int half = 0; half < 2; half++) {
                int r = tm + wm*32 + mt*16 + g + half*8;
                int col = tn + wn*32 + nt*8 + tig*2;
                float v0 = c[mt][nt][half*2+0];
                float v1 = c[mt][nt][half*2+1];
                if (bias) { v0 += bias[col]; v1 += bias[col+1]; }
                if (ep == 1) {
                    v0 += add1[(size_t)r*256 + col]   + add2[(r>>9)*256 + col];
                    v1 += add1[(size_t)r*256 + col+1] + add2[(r>>9)*256 + col+1];
                    float2 o = {v0, v1};
                    *(float2*)(C + (size_t)r*256 + col) = o;
                } else if (ep == 2) {
                    v0 = v0 > 0.f ? v0 : 0.01f*v0;
                    v1 = v1 > 0.f ? v1 : 0.01f*v1;
                    float2 old = *(float2*)(C + (size_t)r*256 + col);
                    float2 o = {old.x + v0, old.y + v1};
                    *(float2*)(C + (size_t)r*256 + col) = o;
                } else if (ep == 3) {
                    int orow = (r>>9)*LP1 + (r & 511) + 1;
                    float2 o = {v0, v1};
                    *(float2*)(C + (size_t)orow*256 + col) = o;
                } else {
                    float2 o = {v0, v1};
                    *(float2*)(C + (size_t)r*256 + col) = o;
                }
            }
        }
    }
}

// ------- GAT attention: factorized-exp weights + tensor-core weighted sum -------
__global__ __launch_bounds__(256) void k_gat_attn2(const float* __restrict__ fcb) {
    extern __shared__ char smraw[];
    unsigned* sgt  = (unsigned*)smraw;               // 512*44
    unsigned* ws   = sgt + 512*44;                   // 256*68
    float*    sej  = (float*)(ws + 256*68);          // 512
    float*    sE   = sej + 512;                      // 512
    float*    sF   = sE + 512;                       // 512
    float4*   sRow = (float4*)(sF + 512);            // 256
    unsigned* sadj = (unsigned*)(sRow + 256);        // 256*16
    float*    sred = (float*)(sadj + 256*16);        // 8

    int n = blockIdx.x & 7, b = blockIdx.x >> 3;
    int i0 = blockIdx.y * 256;
    int tid = threadIdx.x, lane = tid & 31, wrp = tid >> 5;
    int g = lane >> 2, tig = lane & 3;

    for (int l = tid; l < L; l += 256) sej[l] = g_ej[n*BL + b*L + l];
    for (int j = tid; j < L; j += 256) {
        const float4* gr = (const float4*)(g_gbuf + ((size_t)(b*L + j))*ND + n*HD);
        unsigned* dst = sgt + j*44;
        #pragma unroll
        for (int q = 0; q < 8; q++) {
            float4 v = gr[q];
            dst[q*4+0]=f2tf(v.x); dst[q*4+1]=f2tf(v.y);
            dst[q*4+2]=f2tf(v.z); dst[q*4+3]=f2tf(v.w);
        }
        dst[32] = f2tf(1.0f);
        #pragma unroll
        for (int q = 33; q < 40; q++) dst[q] = 0u;
    }
    for (int idx = tid; idx < 256*16; idx += 256)
        sadj[idx] = g_adj[((size_t)(b*L) + i0 + (idx>>4))*LW + (idx & 15)];
    __syncthreads();

    float mx = -1e30f;
    for (int l = tid; l < L; l += 256) mx = fmaxf(mx, sej[l]);
    mx = warp_max(mx);
    if (lane == 0) sred[wrp] = mx;
    __syncthreads();
    float mj = fmaxf(fmaxf(fmaxf(sred[0],sred[1]),fmaxf(sred[2],sred[3])),
                     fmaxf(fmaxf(sred[4],sred[5]),fmaxf(sred[6],sred[7])));
    for (int l = tid; l < L; l += 256) {
        float d = sej[l] - mj;
        sE[l] = __expf(d);
        sF[l] = __expf(0.2f*d);
    }
    for (int rr = 0; rr < 32; rr++) {
        int r = wrp*32 + rr;
        float mxa = -1e30f;
        #pragma unroll
        for (int t = 0; t < LW; t++)
            if ((sadj[r*16 + t] >> lane) & 1u) mxa = fmaxf(mxa, sej[t*32 + lane]);
        mxa = warp_max(mxa);
        if (lane == 0) {
            float4 rc;
            if (mxa < -5e29f) {
                rc = make_float4(0.f, 0.f, 0.f, 1.f);
            } else {
                float eii = g_ei[n*BL + b*L + i0 + r];
                float M = eii + mxa; M = M > 0.f ? M : 0.2f*M;
                rc.x = __expf(fminf(eii + mj - M, 80.f));
                rc.y = __expf(fminf(0.2f*(eii + mj) - M, 80.f));
                rc.z = eii;
                rc.w = 0.f;
            }
            sRow[r] = rc;
        }
    }
    __syncthreads();

    float c[2][5][4];
    #pragma unroll
    for (int mt = 0; mt < 2; mt++)
        #pragma unroll
        for (int nt = 0; nt < 5; nt++)
            #pragma unroll
            for (int i = 0; i < 4; i++) c[mt][nt][i] = 0.f;

    for (int jc = 0; jc < 8; jc++) {
        int jbase = jc*64;
        float ejv0 = sej[jbase + lane],    ejv1 = sej[jbase + 32 + lane];
        float E0   = sE[jbase + lane],     E1   = sE[jbase + 32 + lane];
        float F0   = sF[jbase + lane],     F1   = sF[jbase + 32 + lane];
        for (int rr = 0; rr < 32; rr++) {
            int r = wrp*32 + rr;
            float4 rc = sRow[r];
            unsigned w0 = sadj[r*16 + jc*2], w1 = sadj[r*16 + jc*2 + 1];
            float v0, v1;
            if (rc.w != 0.f) {
                v0 = 1.0f/512.0f; v1 = 1.0f/512.0f;
            } else {
                v0 = ((w0>>lane)&1u) ? ((rc.z + ejv0 > 0.f) ? rc.x*E0 : rc.y*F0) : 0.f;
                v1 = ((w1>>lane)&1u) ? ((rc.z + ejv1 > 0.f) ? rc.x*E1 : rc.y*F1) : 0.f;
            }
            ws[r*68 + lane]      = f2tf(v0);
            ws[r*68 + 32 + lane] = f2tf(v1);
        }
        __syncthreads();
        #pragma unroll
        for (int ks = 0; ks < 64; ks += 8) {
            unsigned af[2][4];
            #pragma unroll
            for (int mt = 0; mt < 2; mt++) {
                int R = wrp*32 + mt*16;
                af[mt][0] = ws[(R+g  )*68 + ks + tig    ];
                af[mt][1] = ws[(R+g+8)*68 + ks + tig    ];
                af[mt][2] = ws[(R+g  )*68 + ks + tig + 4];
                af[mt][3] = ws[(R+g+8)*68 + ks + tig + 4];
            }
            #pragma unroll
            for (int nt = 0; nt < 5; nt++) {
                unsigned bf[2];
                bf[0] = sgt[(jbase+ks+tig  )*44 + nt*8 + g];
                bf[1] = sgt[(jbase+ks+tig+4)*44 + nt*8 + g];
                mma8(c[0][nt], af[0], bf);
                mma8(c[1][nt], af[1], bf);
            }
        }
        __syncthreads();
    }

    #pragma unroll
    for (int mt = 0; mt < 2; mt++) {
        float den0 = __shfl_sync(0xffffffffu, c[mt][4][0], lane & ~3);
        float den8 = __shfl_sync(0xffffffffu, c[mt][4][2], lane & ~3);
        float inv0 = 1.0f / den0, inv8 = 1.0f / den8;
        int r0 = i0 + wrp*32 + mt*16 + g;
        #pragma unroll
        for (int nt = 0; nt < 4; nt++) {
            int col = nt*8 + tig*2;
            float b0 = fcb[n*HD + col], b1 = fcb[n*HD + col + 1];
            float o00 = c[mt][nt][0]*inv0 + b0, o01 = c[mt][nt][1]*inv0 + b1;
            float o10 = c[mt][nt][2]*inv8 + b0, o11 = c[mt][nt][3]*inv8 + b1;
            o00 = o00 > 0.f ? o00 : expm1f(o00);
            o01 = o01 > 0.f ? o01 : expm1f(o01);
            o10 = o10 > 0.f ? o10 : expm1f(o10);
            o11 = o11 > 0.f ? o11 : expm1f(o11);
            float2 a = {o00, o01}, bb = {o10, o11};
            *(float2*)(g_temp + ((size_t)(b*L) + r0    )*ND + n*HD + col) = a;
            *(float2*)(g_temp + ((size_t)(b*L) + r0 + 8)*ND + n*HD + col) = bb;
        }
    }
}

// fused star attention: grid (B, NH), 256 threads
__global__ void k_star(const int* __restrict__ mask) {
    __shared__ float sq[HD];
    __shared__ float sw[LP1];
    __shared__ float redm[8];
    __shared__ float reds[8];
    __shared__ float part[8][HD];
    int b = blockIdx.x, n = blockIdx.y;
    int tid = threadIdx.x, lane = tid & 31, w = tid >> 5;
    if (tid < HD) sq[tid] = g_qproj[b*ND + n*HD + tid];
    __syncthreads();
    const float scale = 0.17677669529663689f;
    const float* kp = g_kproj + (size_t)b*LP1*ND + n*HD;
    for (int l = tid; l < LP1; l += 256) {
        bool valid = (l == 0) || (mask[b*L + l - 1] != 0);
        float s = -1e30f;
        if (valid) {
            const float4* row = (const float4*)(kp + (size_t)l*ND);
            float acc = 0.f;
            #pragma unroll
            for (int q = 0; q < 8; q++) {
                float4 v = row[q];
                acc += v.x*sq[q*4+0] + v.y*sq[q*4+1] + v.z*sq[q*4+2] + v.w*sq[q*4+3];
            }
            s = acc * scale;
        }
        sw[l] = s;
    }
    __syncthreads();
    float mx = -1e30f;
    for (int l = tid; l < LP1; l += 256) mx = fmaxf(mx, sw[l]);
    mx = warp_max(mx);
    if (lane == 0) redm[w] = mx;
    __syncthreads();
    if (w == 0) {
        float v = (lane < 8) ? redm[lane] : -1e30f;
        v = warp_max(v);
        if (lane == 0) redm[0] = v;
    }
    __syncthreads();
    mx = redm[0];
    float sum = 0.f;
    for (int l = tid; l < LP1; l += 256) {
        float e = __expf(sw[l] - mx);
        sw[l] = e;
        sum += e;
    }
    sum = warp_sum(sum);
    if (lane == 0) reds[w] = sum;
    __syncthreads();
    float total = 0.f;
    #pragma unroll
    for (int u = 0; u < 8; u++) total += reds[u];
    float inv = 1.0f / total;
    float acc = 0.f;
    for (int l = w; l < LP1; l += 8)
        acc += sw[l] * kp[(size_t)l*ND + lane];
    part[w][lane] = acc;
    __syncthreads();
    if (w == 0) {
        float a = 0.f;
        #pragma unroll
        for (int u = 0; u < 8; u++) a += part[u][lane];
        g_attv[b*ND + n*HD + lane] = a * inv;
    }
}

// relay = lrelu(attv @ so_w^T + so_b) + fused next-iter relay-dependent prep
__global__ void k_so_fused(const float* __restrict__ sow, const float* __restrict__ sob,
                           const float* __restrict__ a1, const float* __restrict__ a2,
                           const float* __restrict__ sqw_n, const float* __restrict__ sqb_n,
                           int do_next) {
    int b = blockIdx.x, t = threadIdx.x, lane = t & 31, w = t >> 5;
    __shared__ float sa[ND];
    __shared__ float sr[H];
    sa[t] = g_attv[b*ND + t];
    __syncthreads();
    for (int o = 0; o < 32; o++) {
        int h = w*32 + o;
        float acc = 0.f;
        #pragma unroll
        for (int q = 0; q < 8; q++)
            acc += sa[q*32 + lane] * sow[(size_t)h*ND + q*32 + lane];
        acc = warp_sum(acc);
        if (lane == 0) {
            float s = acc + sob[h];
            s = s > 0.f ? s : 0.01f*s;
            g_relay[b*H + h] = s;
            sr[h] = s;
        }
    }
    __syncthreads();
    if (!do_next) return;
    // next-iter: grel
    {
        float s = 0.f;
        #pragma unroll 8
        for (int k = 0; k < H; k++) s += sr[k] * g_Hw[k*ND + t];
        g_grel[b*ND + t] = s;
    }
    // next-iter: r1/r2
    if (t < NH) {
        int n = t; float s1 = 0.f, s2 = 0.f;
        const float* A1 = a1 + n*3*H + H;
        const float* A2 = a2 + n*3*H + H;
        for (int k = 0; k < H; k++) { s1 += sr[k]*A1[2*k+1]; s2 += sr[k]*A2[2*k+1]; }
        g_r1[n*B + b] = s1; g_r2[n*B + b] = s2;
    }
    // next-iter: qproj
    for (int o = 0; o < 32; o++) {
        int c = w*32 + o;
        float acc = 0.f;
        #pragma unroll
        for (int q = 0; q < 8; q++)
            acc += sr[q*32 + lane] * sqw_n[(size_t)c*H + q*32 + lane];
        acc = warp_sum(acc);
        if (lane == 0) g_qproj[b*ND + c] = acc + sqb_n[c];
    }
}

__global__ void k_out(float* __restrict__ out, int total, const int* __restrict__ mask) {
    int idx = blockIdx.x*blockDim.x + threadIdx.x;
    if (idx >= total) return;
    if (idx < BL*H) out[idx] = (mask[idx >> 8] != 0) ? g_nodes[idx] : 0.f;
    else            out[idx] = g_relay[idx - BL*H];
}

// ---------------- launch ----------------
extern "C" void kernel_launch(void* const* d_in, const int* in_sizes, int n_in,
                              void* d_out, int out_size) {
    const float* data    = (const float*)d_in[0];
    const float* WQw     = (const float*)d_in[1];
    const float* WQb     = (const float*)d_in[2];
    const float* a1      = (const float*)d_in[3];
    const float* a2      = (const float*)d_in[4];
    const float* fcw_gat = (const float*)d_in[5];
    const float* fcb_gat = (const float*)d_in[6];
    const float* norm_g  = (const float*)d_in[7];
    const float* norm_b  = (const float*)d_in[8];
    const float* sq_w    = (const float*)d_in[9];
    const float* sq_b    = (const float*)d_in[10];
    const float* sk_w    = (const float*)d_in[11];
    const float* sk_b    = (const float*)d_in[12];
    const float* so_w    = (const float*)d_in[13];
    const float* so_b    = (const float*)d_in[14];
    const float* fc_w    = (const float*)d_in[15];
    const float* fc_b    = (const float*)d_in[16];
    const int*   mask    = (const int*)d_in[17];
    const int*   edge    = (const int*)d_in[18];
    float* out = (float*)d_out;

    const int GAT_SMEM  = (512*44 + 256*68 + 512*3 + 256*4 + 256*16 + 16) * (int)sizeof(float);
    const int GEMM_SMEM = (2*ASZ + 2*BSZ) * (int)sizeof(unsigned);   // 55296
    cudaFuncSetAttribute(k_gat_attn2, cudaFuncAttributeMaxDynamicSharedMemorySize, GAT_SMEM);
    cudaFuncSetAttribute(k_gemm_tf32, cudaFuncAttributeMaxDynamicSharedMemorySize, GEMM_SMEM);

    float *p_nodes, *p_xn, *p_gdat, *p_gbuf, *p_temp, *p_Mcat, *p_Gw, *p_bqF, *p_grel, *p_kproj;
    cudaGetSymbolAddress((void**)&p_nodes, g_nodes);
    cudaGetSymbolAddress((void**)&p_xn,    g_xn);
    cudaGetSymbolAddress((void**)&p_gdat,  g_gdat);
    cudaGetSymbolAddress((void**)&p_gbuf,  g_gbuf);
    cudaGetSymbolAddress((void**)&p_temp,  g_temp);
    cudaGetSymbolAddress((void**)&p_Mcat,  g_Mcat);
    cudaGetSymbolAddress((void**)&p_Gw,    g_Gw);
    cudaGetSymbolAddress((void**)&p_bqF,   g_bqF);
    cudaGetSymbolAddress((void**)&p_grel,  g_grel);
    cudaGetSymbolAddress((void**)&p_kproj, g_kproj);

    cudaMemcpyAsync(p_nodes, data, sizeof(float)*BL*H, cudaMemcpyDeviceToDevice);
    cudaMemsetAsync(p_Mcat, 0, sizeof(float)*H*ND);

    k_pack_adj<<<1024, 256>>>(edge);
    k_prep_small<<<288, 256>>>(data, WQw, WQb, a1, a2, fcw_gat);
    k_prep_Mcat<<<dim3(NH, 2), 256>>>(WQw, fcw_gat);
    k_d12<<<1024, 256>>>(data, a1, a2);
    k_gemm_tf32<<<dim3(64, 4), 256, GEMM_SMEM>>>(data, p_Gw, p_gdat, 0, 0,
                                                 nullptr, nullptr, nullptr);
    k_relay_small<<<dim3(B, 2), 256>>>(a1, a2, sq_w, sq_b);   // iter-0 relay deps

    for (int i = 0; i < ITR; i++) {
        k_ln_eij<<<1024, 256>>>(norm_g + i*H, norm_b + i*H, i > 0 ? 1 : 0, mask);
        // g = xn @ Mcat + bqF + gdat + grel
        k_gemm_tf32<<<dim3(64, 4), 256, GEMM_SMEM>>>(p_xn, p_Mcat, p_gbuf, 0, 1,
                                                     p_bqF, p_gdat, p_grel);
        k_gat_attn2<<<dim3(NH*B, 2), 256, GAT_SMEM>>>(fcb_gat);
        // nodes += lrelu(temp @ fc_w + fc_b)
        k_gemm_tf32<<<dim3(64, 4), 256, GEMM_SMEM>>>(p_temp, fc_w, p_nodes, 0, 2,
                                                     fc_b, nullptr, nullptr);
        // kproj (rows 1..512) + fused row 0 via 65th block column
        k_gemm_tf32<<<dim3(65, 4), 256, GEMM_SMEM>>>(p_nodes, sk_w + (size_t)i*ND*H,
                                                     p_kproj, 1, 3,
                                                     sk_b + i*ND, nullptr, nullptr);
        k_star<<<dim3(B, NH), 256>>>(mask);
        int nx = (i + 1 < ITR) ? (i + 1) : 0;
        k_so_fused<<<B, 256>>>(so_w + (size_t)i*H*ND, so_b + i*H, a1, a2,
                               sq_w + (size_t)nx*ND*H, sq_b + nx*ND, i + 1 < ITR);
    }

    int total = BL*H + B*H;
    if (total > out_size) total = out_size;
    k_out<<<(total + 255)/256, 256>>>(out, total, mask);
}